// round 12
// baseline (speedup 1.0000x reference)
#include <cuda_runtime.h>
#include <cuda_fp16.h>
#include <math.h>
#include <stdint.h>

// Problem constants
#define BB   2
#define NN   2048
#define DD   1024
#define HH   16
#define HDD  64
#define BSZ  64
#define MM   32
#define MAXK 32
#define SCALEF 0.125f
#define TOK  (BB * NN)

// ---------------- scratch ----------------
__device__ float g_qkv [TOK * 3 * DD];        // fp32 qkv (pool/mask)
__device__ float g_qb  [BB * HH * MM * HDD];
__device__ float g_kb  [BB * HH * MM * HDD];
__device__ int   g_kept[BB * HH * MM * MAXK];
__device__ int   g_kcnt[BB * HH * MM];
__device__ __half g_xh [TOK * DD];            // x fp16
__device__ __half g_wq [3 * DD * DD];         // weights fp16
__device__ __half g_wp [DD * DD];
__device__ __half g_ah [TOK * DD];            // attn out fp16
// attention operands produced by QKV epilogue:
__device__ __half g_qh2[TOK * DD], g_ql2[TOK * DD];   // q*0.125 hi/lo
__device__ __half g_kh2[TOK * DD], g_kl2[TOK * DD];   // k hi/lo
__device__ __half g_vf [TOK * DD];                    // v single

// =====================================================================
// helpers
// =====================================================================
static __device__ __forceinline__ uint32_t pack2f16(float a, float b) {
    return (uint32_t)__half_as_ushort(__float2half_rn(a)) |
           ((uint32_t)__half_as_ushort(__float2half_rn(b)) << 16);
}
static __device__ __forceinline__ uint32_t smem_u32(const void* p) {
    uint32_t a;
    asm("{ .reg .u64 t; cvta.to.shared.u64 t, %1; cvt.u32.u64 %0, t; }"
        : "=r"(a) : "l"(p));
    return a;
}
static __device__ __forceinline__ void cp16(uint32_t s, const void* g) {
    asm volatile("cp.async.cg.shared.global [%0], [%1], 16;"
                 :: "r"(s), "l"(g) : "memory");
}
static __device__ __forceinline__ void ldm4(uint32_t* r, uint32_t a) {
    asm volatile("ldmatrix.sync.aligned.m8n8.x4.shared.b16 {%0,%1,%2,%3}, [%4];"
        : "=r"(r[0]), "=r"(r[1]), "=r"(r[2]), "=r"(r[3]) : "r"(a));
}
static __device__ __forceinline__ void ldm4t(uint32_t* r, uint32_t a) {
    asm volatile("ldmatrix.sync.aligned.m8n8.x4.trans.shared.b16 {%0,%1,%2,%3}, [%4];"
        : "=r"(r[0]), "=r"(r[1]), "=r"(r[2]), "=r"(r[3]) : "r"(a));
}
// split pair (a,b) into hi/lo fp16 and store packed
static __device__ __forceinline__ void store_split(
    __half* hi, __half* lo, size_t off, float a, float b)
{
    __half ha = __float2half_rn(a), hb = __float2half_rn(b);
    *(uint32_t*)(hi + off) = (uint32_t)__half_as_ushort(ha) |
                             ((uint32_t)__half_as_ushort(hb) << 16);
    *(uint32_t*)(lo + off) = pack2f16(a - __half2float(ha), b - __half2float(hb));
}

#define MMA_F16(c, a, b)                                                   \
    asm volatile("mma.sync.aligned.m16n8k16.row.col.f32.f16.f16.f32 "      \
        "{%0,%1,%2,%3}, {%4,%5,%6,%7}, {%8,%9}, {%0,%1,%2,%3};"            \
        : "+f"((c)[0]), "+f"((c)[1]), "+f"((c)[2]), "+f"((c)[3])           \
        : "r"((a)[0]), "r"((a)[1]), "r"((a)[2]), "r"((a)[3]),              \
          "r"((b)[0]), "r"((b)[1]))

// =====================================================================
// fused fp32 -> fp16 convert for x, qkv_w, proj_w
// =====================================================================
#define N4_X (TOK * DD / 4)
#define N4_WQ (3 * DD * DD / 4)
#define N4_WP (DD * DD / 4)

__global__ __launch_bounds__(256) void split3_kernel(
    const float* __restrict__ sx, __half* __restrict__ xh,
    const float* __restrict__ sq, __half* __restrict__ wq,
    const float* __restrict__ sp, __half* __restrict__ wp)
{
    int i = blockIdx.x * blockDim.x + threadIdx.x;
    const float* src; __half* dst;
    if (i < N4_X) { src = sx; dst = xh; }
    else if (i < N4_X + N4_WQ) { i -= N4_X; src = sq; dst = wq; }
    else { i -= N4_X + N4_WQ; if (i >= N4_WP) return; src = sp; dst = wp; }
    float4 v = ((const float4*)src)[i];
    uint2 ph;
    ph.x = pack2f16(v.x, v.y); ph.y = pack2f16(v.z, v.w);
    ((uint2*)dst)[i] = ph;
}

// =====================================================================
// fp16 single-pass warp-MMA GEMM (NT).
// MODE 0 (QKV): writes fp32 C AND the fp16 attention operands
//               (qh/ql scaled, kh/kl, vf) in the epilogue.
// MODE 1 (proj): C = A*B + bias (fp32).
// =====================================================================
#define PADK 72
#define TILE_E (128 * PADK)
#define STAGE_B (2u * TILE_E * 2u)
#define GEMM_SMEM (2u * STAGE_B)

template <int MODE>
__global__ __launch_bounds__(256, 2) void gemm_mma(
    const __half* __restrict__ Ah_, const __half* __restrict__ Bh_,
    const float* __restrict__ bias, float* __restrict__ C,
    int Nc, int K)
{
    extern __shared__ __align__(16) uint16_t smg[];
    const uint32_t sbase = smem_u32(smg);

    const int tid  = threadIdx.x;
    const int wid  = tid >> 5;
    const int lane = tid & 31;
    const int wm   = wid & 1;
    const int wn   = wid >> 1;
    const int bm   = blockIdx.y * 128;
    const int bn   = blockIdx.x * 128;

    int crow[4]; uint32_t cdst[4]; int ccol[4];
#pragma unroll
    for (int j = 0; j < 4; j++) {
        int lin = tid + (j << 8);
        crow[j] = lin >> 3;
        ccol[j] = (lin & 7) << 3;
        cdst[j] = (uint32_t)(crow[j] * PADK * 2 + (lin & 7) * 16);
    }

    uint32_t aoff[4];
#pragma unroll
    for (int mt = 0; mt < 4; mt++) {
        int mrow = wm * 64 + mt * 16 + (lane & 15);
        int ke   = (lane >> 4) << 3;
        aoff[mt] = (uint32_t)((mrow * PADK + ke) * 2);
    }
    uint32_t boff[2];
#pragma unroll
    for (int np = 0; np < 2; np++) {
        int nrow = wn * 32 + np * 16 + ((lane >> 4) << 3) + (lane & 7);
        int ke   = ((lane >> 3) & 1) << 3;
        boff[np] = (uint32_t)((nrow * PADK + ke) * 2);
    }

    float acc[4][4][4];
#pragma unroll
    for (int mt = 0; mt < 4; mt++)
#pragma unroll
        for (int nt = 0; nt < 4; nt++)
#pragma unroll
            for (int r = 0; r < 4; r++) acc[mt][nt][r] = 0.0f;

    const int NCH = K >> 6;

    auto issue = [&](int ch, int st) {
        const int k0 = ch << 6;
        const uint32_t stg = sbase + (uint32_t)st * STAGE_B;
#pragma unroll
        for (int j = 0; j < 4; j++) {
            size_t offA = (size_t)(bm + crow[j]) * K + k0 + ccol[j];
            size_t offB = (size_t)(bn + crow[j]) * K + k0 + ccol[j];
            cp16(stg + cdst[j],              Ah_ + offA);
            cp16(stg + TILE_E * 2 + cdst[j], Bh_ + offB);
        }
    };

    issue(0, 0);
    asm volatile("cp.async.commit_group;" ::: "memory");

    for (int ch = 0; ch < NCH; ch++) {
        if (ch + 1 < NCH) issue(ch + 1, (ch + 1) & 1);
        asm volatile("cp.async.commit_group;" ::: "memory");
        asm volatile("cp.async.wait_group 1;" ::: "memory");
        __syncthreads();

        const uint32_t stg = sbase + (uint32_t)(ch & 1) * STAGE_B;

#pragma unroll
        for (int ks = 0; ks < 4; ks++) {
            const uint32_t kadd = (uint32_t)(ks << 5);
            uint32_t fah[4][4], fbh[2][4];
#pragma unroll
            for (int mt = 0; mt < 4; mt++)
                ldm4(fah[mt], stg + aoff[mt] + kadd);
#pragma unroll
            for (int np = 0; np < 2; np++)
                ldm4(fbh[np], stg + TILE_E * 2 + boff[np] + kadd);
#pragma unroll
            for (int mt = 0; mt < 4; mt++)
#pragma unroll
                for (int nt = 0; nt < 4; nt++)
                    MMA_F16(acc[mt][nt], fah[mt], &fbh[nt >> 1][(nt & 1) << 1]);
        }
        __syncthreads();
    }

    const int g = lane >> 2;
    const int t = lane & 3;
#pragma unroll
    for (int nt = 0; nt < 4; nt++) {
        int col = bn + wn * 32 + nt * 8 + t * 2;
        float b0v = (MODE == 1) ? bias[col]     : 0.0f;
        float b1v = (MODE == 1) ? bias[col + 1] : 0.0f;
#pragma unroll
        for (int mt = 0; mt < 4; mt++) {
            int row = bm + wm * 64 + mt * 16 + g;
            float a0 = acc[mt][nt][0] + b0v, a1 = acc[mt][nt][1] + b1v;
            float a2 = acc[mt][nt][2] + b0v, a3 = acc[mt][nt][3] + b1v;
            float2 lo2 = {a0, a1}, hi2 = {a2, a3};
            *(float2*)(C + (size_t)row * Nc + col)       = lo2;
            *(float2*)(C + (size_t)(row + 8) * Nc + col) = hi2;
            if (MODE == 0) {
                const int sec = col >> 10;        // 0=q, 1=k, 2=v
                const int cc  = col & 1023;
                size_t o0 = (size_t)row * DD + cc;
                size_t o1 = (size_t)(row + 8) * DD + cc;
                if (sec == 0) {
                    store_split(g_qh2, g_ql2, o0, a0 * SCALEF, a1 * SCALEF);
                    store_split(g_qh2, g_ql2, o1, a2 * SCALEF, a3 * SCALEF);
                } else if (sec == 1) {
                    store_split(g_kh2, g_kl2, o0, a0, a1);
                    store_split(g_kh2, g_kl2, o1, a2, a3);
                } else {
                    *(uint32_t*)(g_vf + o0) = pack2f16(a0, a1);
                    *(uint32_t*)(g_vf + o1) = pack2f16(a2, a3);
                }
            }
        }
    }
}

// =====================================================================
// Block-mean pooling
// =====================================================================
__global__ __launch_bounds__(64) void pool_kernel()
{
    const int row = blockIdx.x;
    const int d   = threadIdx.x;
    const int m   = row % MM;
    const int b   = row / (MM * HH);
    const int h   = (row / MM) % HH;

    const float* base = g_qkv + ((size_t)(b * NN + m * BSZ) * (3 * DD)) + h * HDD + d;
    float sq = 0.0f, sk = 0.0f;
    for (int i = 0; i < BSZ; i++) {
        sq += base[(size_t)i * 3 * DD];
        sk += base[(size_t)i * 3 * DD + DD];
    }
    g_qb[(size_t)row * HDD + d] = sq * (1.0f / BSZ);
    g_kb[(size_t)row * HDD + d] = sk * (1.0f / BSZ);
}

// =====================================================================
// Block scores + top-2 threshold + diagonal keep (8 warps/block)
// =====================================================================
__global__ __launch_bounds__(256) void mask_kernel()
{
    const int lane = threadIdx.x & 31;
    const int row  = blockIdx.x * 8 + (threadIdx.x >> 5);
    const int m    = row % MM;
    const int bh   = row / MM;

    const float* qb = g_qb + (size_t)row * HDD;
    const float* kb = g_kb + ((size_t)bh * MM + lane) * HDD;

    float s = 0.0f;
#pragma unroll
    for (int d4 = 0; d4 < 16; d4++) {
        float4 qv = *(const float4*)(qb + (d4 << 2));
        float4 kv = *(const float4*)(kb + (d4 << 2));
        s = fmaf(qv.x, kv.x, s); s = fmaf(qv.y, kv.y, s);
        s = fmaf(qv.z, kv.z, s); s = fmaf(qv.w, kv.w, s);
    }
    s *= SCALEF;

    const unsigned FULL = 0xffffffffu;
    float m1 = s;
#pragma unroll
    for (int off = 16; off; off >>= 1) m1 = fmaxf(m1, __shfl_xor_sync(FULL, m1, off));
    unsigned b1 = __ballot_sync(FULL, s == m1);
    int lead = __ffs(b1) - 1;
    float v2 = (lane == lead) ? -INFINITY : s;
    float m2 = v2;
#pragma unroll
    for (int off = 16; off; off >>= 1) m2 = fmaxf(m2, __shfl_xor_sync(FULL, m2, off));

    bool keep = (s >= m2) || (lane == m);
    unsigned km = __ballot_sync(FULL, keep);
    if (lane == 0) g_kcnt[row] = __popc(km);
    if (keep) {
        int pos = __popc(km & ((1u << lane) - 1u));
        g_kept[(size_t)row * MAXK + pos] = lane;
    }
}

// =====================================================================
// Sparse block attention on tensor cores, all-fp16 operands via
// cp.async (no in-kernel conversion), 2-stage K/V pipeline.
// smem (half elems): [0,4608) qh, [4608,9216) ql,
//   stage s at 9216 + s*13824: kh(4608) kl(4608) vf(4608); APAD=72.
// =====================================================================
#define APAD 72
#define ATQH 0u
#define ATQL 4608u
#define ATS0 9216u
#define ATSTG 13824u
#define ATT_SMEM 73728u

__global__ __launch_bounds__(128) void attn_kernel()
{
    extern __shared__ __align__(16) __half sma[];
    const uint32_t sb = smem_u32(sma);

    const int tid  = threadIdx.x;
    const int wid  = tid >> 5;
    const int lane = tid & 31;
    const int row  = blockIdx.x;
    const int m    = row % MM;
    const int h    = (row / MM) % HH;
    const int b    = row / (MM * HH);
    const int tok0 = b * NN + m * BSZ;
    const size_t hoff = (size_t)h * HDD;

    const int cnt = g_kcnt[row];
    const int* kept = g_kept + (size_t)row * MAXK;

    // per-thread cp.async piece coords
    const int pr = tid >> 3;           // rows: pr, pr+16, pr+32, pr+48
    const int pc = (tid & 7) << 3;     // elem col (8 fp16 = 16B)

    // prologue: Q (hi/lo) + tile0 in one group
    {
#pragma unroll
        for (int j = 0; j < 4; j++) {
            int r = pr + (j << 4);
            size_t g = (size_t)(tok0 + r) * DD + hoff + pc;
            uint32_t so = sb + (uint32_t)((r * APAD + pc) << 1);
            cp16(so + (ATQH << 1), g_qh2 + g);
            cp16(so + (ATQL << 1), g_ql2 + g);
        }
        const int kt = b * NN + kept[0] * BSZ;
#pragma unroll
        for (int j = 0; j < 4; j++) {
            int r = pr + (j << 4);
            size_t g = (size_t)(kt + r) * DD + hoff + pc;
            uint32_t so = sb + (uint32_t)((ATS0 + r * APAD + pc) << 1);
            cp16(so,                 g_kh2 + g);
            cp16(so + (4608u << 1),  g_kl2 + g);
            cp16(so + (9216u << 1),  g_vf  + g);
        }
        asm volatile("cp.async.commit_group;" ::: "memory");
    }

    // fragment offsets
    uint32_t qab;
    {
        int mrow = wid * 16 + (lane & 15);
        qab = sb + (uint32_t)((mrow * APAD + ((lane >> 4) << 3)) << 1);
    }
    uint32_t kboff[4], voff[4];
#pragma unroll
    for (int np = 0; np < 4; np++) {
        int nrow = np * 16 + ((lane >> 4) << 3) + (lane & 7);
        int ke   = ((lane >> 3) & 1) << 3;
        kboff[np] = (uint32_t)((nrow * APAD + ke) << 1);
    }
#pragma unroll
    for (int dp = 0; dp < 4; dp++) {
        int vrow = (((lane >> 3) & 1) << 3) + (lane & 7);
        int vcol = dp * 16 + ((lane >> 4) << 3);
        voff[dp] = (uint32_t)((vrow * APAD + vcol) << 1);
    }

    uint32_t qh_a[4][4], ql_a[4][4];
    float c_o[8][4];
#pragma unroll
    for (int dt = 0; dt < 8; dt++)
#pragma unroll
        for (int r = 0; r < 4; r++) c_o[dt][r] = 0.0f;
    float mrun0 = -INFINITY, mrun1 = -INFINITY, lrun0 = 0.0f, lrun1 = 0.0f;

    for (int kbi = 0; kbi < cnt; kbi++) {
        if (kbi + 1 < cnt) {
            const int kt = b * NN + kept[kbi + 1] * BSZ;
            const uint32_t stb = ATS0 + (uint32_t)((kbi + 1) & 1) * ATSTG;
#pragma unroll
            for (int j = 0; j < 4; j++) {
                int r = pr + (j << 4);
                size_t g = (size_t)(kt + r) * DD + hoff + pc;
                uint32_t so = sb + (uint32_t)((stb + r * APAD + pc) << 1);
                cp16(so,                g_kh2 + g);
                cp16(so + (4608u << 1), g_kl2 + g);
                cp16(so + (9216u << 1), g_vf  + g);
            }
        }
        asm volatile("cp.async.commit_group;" ::: "memory");
        if (kbi + 1 < cnt)
            asm volatile("cp.async.wait_group 1;" ::: "memory");
        else
            asm volatile("cp.async.wait_group 0;" ::: "memory");
        __syncthreads();

        if (kbi == 0) {
#pragma unroll
            for (int ks = 0; ks < 4; ks++) {
                ldm4(qh_a[ks], qab + (ATQH << 1) + ks * 32);
                ldm4(ql_a[ks], qab + (ATQL << 1) + ks * 32);
            }
        }

        const uint32_t stg = sb + (uint32_t)((ATS0 + (uint32_t)(kbi & 1) * ATSTG) << 1);

        // ---- S = Q K^T (3 passes) ----
        float c_s[8][4];
#pragma unroll
        for (int nt = 0; nt < 8; nt++)
#pragma unroll
            for (int r = 0; r < 4; r++) c_s[nt][r] = 0.0f;
#pragma unroll
        for (int ks = 0; ks < 4; ks++) {
            uint32_t kh[4][4], kl[4][4];
#pragma unroll
            for (int np = 0; np < 4; np++) {
                ldm4(kh[np], stg + kboff[np] + ks * 32);
                ldm4(kl[np], stg + (4608u << 1) + kboff[np] + ks * 32);
            }
#pragma unroll
            for (int nt = 0; nt < 8; nt++)
                MMA_F16(c_s[nt], qh_a[ks], &kh[nt >> 1][(nt & 1) << 1]);
#pragma unroll
            for (int nt = 0; nt < 8; nt++)
                MMA_F16(c_s[nt], qh_a[ks], &kl[nt >> 1][(nt & 1) << 1]);
#pragma unroll
            for (int nt = 0; nt < 8; nt++)
                MMA_F16(c_s[nt], ql_a[ks], &kh[nt >> 1][(nt & 1) << 1]);
        }

        // ---- online softmax on fragments ----
        const unsigned FULL = 0xffffffffu;
        float rmax0 = -INFINITY, rmax1 = -INFINITY;
#pragma unroll
        for (int nt = 0; nt < 8; nt++) {
            rmax0 = fmaxf(rmax0, fmaxf(c_s[nt][0], c_s[nt][1]));
            rmax1 = fmaxf(rmax1, fmaxf(c_s[nt][2], c_s[nt][3]));
        }
        rmax0 = fmaxf(rmax0, __shfl_xor_sync(FULL, rmax0, 1));
        rmax0 = fmaxf(rmax0, __shfl_xor_sync(FULL, rmax0, 2));
        rmax1 = fmaxf(rmax1, __shfl_xor_sync(FULL, rmax1, 1));
        rmax1 = fmaxf(rmax1, __shfl_xor_sync(FULL, rmax1, 2));

        float mn0 = fmaxf(mrun0, rmax0), mn1 = fmaxf(mrun1, rmax1);
        float e0 = __expf(mrun0 - mn0),  e1 = __expf(mrun1 - mn1);
        float rs0 = 0.0f, rs1 = 0.0f;
#pragma unroll
        for (int nt = 0; nt < 8; nt++) {
            c_s[nt][0] = __expf(c_s[nt][0] - mn0); rs0 += c_s[nt][0];
            c_s[nt][1] = __expf(c_s[nt][1] - mn0); rs0 += c_s[nt][1];
            c_s[nt][2] = __expf(c_s[nt][2] - mn1); rs1 += c_s[nt][2];
            c_s[nt][3] = __expf(c_s[nt][3] - mn1); rs1 += c_s[nt][3];
        }
        rs0 += __shfl_xor_sync(FULL, rs0, 1); rs0 += __shfl_xor_sync(FULL, rs0, 2);
        rs1 += __shfl_xor_sync(FULL, rs1, 1); rs1 += __shfl_xor_sync(FULL, rs1, 2);
        lrun0 = lrun0 * e0 + rs0;  lrun1 = lrun1 * e1 + rs1;
        mrun0 = mn0;               mrun1 = mn1;
#pragma unroll
        for (int dt = 0; dt < 8; dt++) {
            c_o[dt][0] *= e0; c_o[dt][1] *= e0;
            c_o[dt][2] *= e1; c_o[dt][3] *= e1;
        }

        // ---- O += P V (P split hi/lo, V single) ----
#pragma unroll
        for (int ks = 0; ks < 4; ks++) {
            uint32_t pA[4], pL[4];
#pragma unroll
            for (int half = 0; half < 2; half++) {
                const float* cs = c_s[2 * ks + half];
                float x0 = cs[0], x1 = cs[1], x2 = cs[2], x3 = cs[3];
                __half h0 = __float2half_rn(x0), h1 = __float2half_rn(x1);
                __half h2 = __float2half_rn(x2), h3 = __float2half_rn(x3);
                pA[2 * half]     = (uint32_t)__half_as_ushort(h0) |
                                   ((uint32_t)__half_as_ushort(h1) << 16);
                pA[2 * half + 1] = (uint32_t)__half_as_ushort(h2) |
                                   ((uint32_t)__half_as_ushort(h3) << 16);
                pL[2 * half]     = pack2f16(x0 - __half2float(h0),
                                            x1 - __half2float(h1));
                pL[2 * half + 1] = pack2f16(x2 - __half2float(h2),
                                            x3 - __half2float(h3));
            }
            uint32_t vf[4][4];
#pragma unroll
            for (int dp = 0; dp < 4; dp++)
                ldm4t(vf[dp], stg + (9216u << 1) + voff[dp]
                              + (uint32_t)(ks * 16 * APAD * 2));
#pragma unroll
            for (int dt = 0; dt < 8; dt++)
                MMA_F16(c_o[dt], pA, &vf[dt >> 1][(dt & 1) << 1]);
#pragma unroll
            for (int dt = 0; dt < 8; dt++)
                MMA_F16(c_o[dt], pL, &vf[dt >> 1][(dt & 1) << 1]);
        }
        __syncthreads();   // stage reads done before next overwrite
    }

    // ---- epilogue: normalize, single fp16 store ----
    const float inv0 = 1.0f / lrun0, inv1 = 1.0f / lrun1;
    const int g = lane >> 2, t = lane & 3;
    const int tk = tok0 + wid * 16 + g;
    const size_t o0 = (size_t)tk * DD + hoff;
    const size_t o1 = o0 + (size_t)8 * DD;
#pragma unroll
    for (int dt = 0; dt < 8; dt++) {
        int col = dt * 8 + t * 2;
        *(uint32_t*)(g_ah + o0 + col) = pack2f16(c_o[dt][0] * inv0, c_o[dt][1] * inv0);
        *(uint32_t*)(g_ah + o1 + col) = pack2f16(c_o[dt][2] * inv1, c_o[dt][3] * inv1);
    }
}

// =====================================================================
// Launch
// =====================================================================
extern "C" void kernel_launch(void* const* d_in, const int* in_sizes, int n_in,
                              void* d_out, int out_size)
{
    const float* x = nullptr; const float* qkv_w = nullptr;
    const float* proj_w = nullptr; const float* proj_b = nullptr;
    for (int i = 0; i < n_in; i++) {
        if      (in_sizes[i] == BB * NN * DD) x      = (const float*)d_in[i];
        else if (in_sizes[i] == 3 * DD * DD)  qkv_w  = (const float*)d_in[i];
        else if (in_sizes[i] == DD * DD)      proj_w = (const float*)d_in[i];
        else if (in_sizes[i] == DD)           proj_b = (const float*)d_in[i];
    }
    float* out = (float*)d_out;

    void* p;
    cudaGetSymbolAddress(&p, g_qkv); float* qkv = (float*)p;
    __half *xh, *wq, *wp, *ah;
    cudaGetSymbolAddress(&p, g_xh); xh = (__half*)p;
    cudaGetSymbolAddress(&p, g_wq); wq = (__half*)p;
    cudaGetSymbolAddress(&p, g_wp); wp = (__half*)p;
    cudaGetSymbolAddress(&p, g_ah); ah = (__half*)p;

    static int attr_done = 0;
    if (!attr_done) {
        cudaFuncSetAttribute(gemm_mma<0>, cudaFuncAttributeMaxDynamicSharedMemorySize, GEMM_SMEM);
        cudaFuncSetAttribute(gemm_mma<1>, cudaFuncAttributeMaxDynamicSharedMemorySize, GEMM_SMEM);
        cudaFuncSetAttribute(attn_kernel, cudaFuncAttributeMaxDynamicSharedMemorySize, ATT_SMEM);
        attr_done = 1;
    }

    {
        int n4 = N4_X + N4_WQ + N4_WP;
        split3_kernel<<<(n4 + 255) / 256, 256>>>(x, xh, qkv_w, wq, proj_w, wp);
    }
    gemm_mma<0><<<dim3(3 * DD / 128, TOK / 128), 256, GEMM_SMEM>>>(
        xh, wq, nullptr, qkv, 3 * DD, DD);
    pool_kernel<<<BB * HH * MM, 64>>>();
    mask_kernel<<<BB * HH * MM / 8, 256>>>();
    attn_kernel<<<BB * HH * MM, 128, ATT_SMEM>>>();
    gemm_mma<1><<<dim3(DD / 128, TOK / 128), 256, GEMM_SMEM>>>(
        ah, wp, proj_b, out, DD, DD);
}

// round 13
// speedup vs baseline: 1.0850x; 1.0850x over previous
#include <cuda_runtime.h>
#include <cuda_fp16.h>
#include <math.h>
#include <stdint.h>

// Problem constants
#define BB   2
#define NN   2048
#define DD   1024
#define HH   16
#define HDD  64
#define BSZ  64
#define MM   32
#define MAXK 32
#define SCALEF 0.125f
#define TOK  (BB * NN)

// ---------------- scratch ----------------
__device__ float g_qb  [BB * HH * MM * HDD];
__device__ float g_kb  [BB * HH * MM * HDD];
__device__ int   g_kept[BB * HH * MM * MAXK];
__device__ int   g_kcnt[BB * HH * MM];
__device__ __half g_xh [TOK * DD];            // x fp16
__device__ __half g_wq [3 * DD * DD];         // weights fp16
__device__ __half g_wp [DD * DD];
__device__ __half g_ah [TOK * DD];            // attn out fp16
// attention operands produced by QKV epilogue:
__device__ __half g_qh2[TOK * DD], g_ql2[TOK * DD];   // q*0.125 hi/lo
__device__ __half g_kh2[TOK * DD], g_kl2[TOK * DD];   // k hi/lo
__device__ __half g_vf [TOK * DD];                    // v single

// =====================================================================
// helpers
// =====================================================================
static __device__ __forceinline__ uint32_t pack2f16(float a, float b) {
    return (uint32_t)__half_as_ushort(__float2half_rn(a)) |
           ((uint32_t)__half_as_ushort(__float2half_rn(b)) << 16);
}
static __device__ __forceinline__ uint32_t smem_u32(const void* p) {
    uint32_t a;
    asm("{ .reg .u64 t; cvta.to.shared.u64 t, %1; cvt.u32.u64 %0, t; }"
        : "=r"(a) : "l"(p));
    return a;
}
static __device__ __forceinline__ void cp16(uint32_t s, const void* g) {
    asm volatile("cp.async.cg.shared.global [%0], [%1], 16;"
                 :: "r"(s), "l"(g) : "memory");
}
static __device__ __forceinline__ void ldm4(uint32_t* r, uint32_t a) {
    asm volatile("ldmatrix.sync.aligned.m8n8.x4.shared.b16 {%0,%1,%2,%3}, [%4];"
        : "=r"(r[0]), "=r"(r[1]), "=r"(r[2]), "=r"(r[3]) : "r"(a));
}
static __device__ __forceinline__ void ldm4t(uint32_t* r, uint32_t a) {
    asm volatile("ldmatrix.sync.aligned.m8n8.x4.trans.shared.b16 {%0,%1,%2,%3}, [%4];"
        : "=r"(r[0]), "=r"(r[1]), "=r"(r[2]), "=r"(r[3]) : "r"(a));
}
static __device__ __forceinline__ void store_split(
    __half* hi, __half* lo, size_t off, float a, float b)
{
    __half ha = __float2half_rn(a), hb = __float2half_rn(b);
    *(uint32_t*)(hi + off) = (uint32_t)__half_as_ushort(ha) |
                             ((uint32_t)__half_as_ushort(hb) << 16);
    *(uint32_t*)(lo + off) = pack2f16(a - __half2float(ha), b - __half2float(hb));
}

#define MMA_F16(c, a, b)                                                   \
    asm volatile("mma.sync.aligned.m16n8k16.row.col.f32.f16.f16.f32 "      \
        "{%0,%1,%2,%3}, {%4,%5,%6,%7}, {%8,%9}, {%0,%1,%2,%3};"            \
        : "+f"((c)[0]), "+f"((c)[1]), "+f"((c)[2]), "+f"((c)[3])           \
        : "r"((a)[0]), "r"((a)[1]), "r"((a)[2]), "r"((a)[3]),              \
          "r"((b)[0]), "r"((b)[1]))

// =====================================================================
// fused fp32 -> fp16 convert for x, qkv_w, proj_w
// =====================================================================
#define N4_X (TOK * DD / 4)
#define N4_WQ (3 * DD * DD / 4)
#define N4_WP (DD * DD / 4)

__global__ __launch_bounds__(256) void split3_kernel(
    const float* __restrict__ sx, __half* __restrict__ xh,
    const float* __restrict__ sq, __half* __restrict__ wq,
    const float* __restrict__ sp, __half* __restrict__ wp)
{
    int i = blockIdx.x * blockDim.x + threadIdx.x;
    const float* src; __half* dst;
    if (i < N4_X) { src = sx; dst = xh; }
    else if (i < N4_X + N4_WQ) { i -= N4_X; src = sq; dst = wq; }
    else { i -= N4_X + N4_WQ; if (i >= N4_WP) return; src = sp; dst = wp; }
    float4 v = ((const float4*)src)[i];
    uint2 ph;
    ph.x = pack2f16(v.x, v.y); ph.y = pack2f16(v.z, v.w);
    ((uint2*)dst)[i] = ph;
}

// =====================================================================
// fp16 single-pass warp-MMA GEMM (NT).
// MODE 0 (QKV): epilogue writes ONLY fp16 attention operands
//   (qh/ql scaled, kh/kl, vf) and the q/k block means (register
//   reduction; each (block,col) owned by exactly one warp).
// MODE 1 (proj): C = A*B + bias (fp32).
// =====================================================================
#define PADK 72
#define TILE_E (128 * PADK)
#define STAGE_B (2u * TILE_E * 2u)
#define GEMM_SMEM (2u * STAGE_B)

template <int MODE>
__global__ __launch_bounds__(256, 2) void gemm_mma(
    const __half* __restrict__ Ah_, const __half* __restrict__ Bh_,
    const float* __restrict__ bias, float* __restrict__ C,
    int Nc, int K)
{
    extern __shared__ __align__(16) uint16_t smg[];
    const uint32_t sbase = smem_u32(smg);

    const int tid  = threadIdx.x;
    const int wid  = tid >> 5;
    const int lane = tid & 31;
    const int wm   = wid & 1;
    const int wn   = wid >> 1;
    const int bm   = blockIdx.y * 128;
    const int bn   = blockIdx.x * 128;

    int crow[4]; uint32_t cdst[4]; int ccol[4];
#pragma unroll
    for (int j = 0; j < 4; j++) {
        int lin = tid + (j << 8);
        crow[j] = lin >> 3;
        ccol[j] = (lin & 7) << 3;
        cdst[j] = (uint32_t)(crow[j] * PADK * 2 + (lin & 7) * 16);
    }

    uint32_t aoff[4];
#pragma unroll
    for (int mt = 0; mt < 4; mt++) {
        int mrow = wm * 64 + mt * 16 + (lane & 15);
        int ke   = (lane >> 4) << 3;
        aoff[mt] = (uint32_t)((mrow * PADK + ke) * 2);
    }
    uint32_t boff[2];
#pragma unroll
    for (int np = 0; np < 2; np++) {
        int nrow = wn * 32 + np * 16 + ((lane >> 4) << 3) + (lane & 7);
        int ke   = ((lane >> 3) & 1) << 3;
        boff[np] = (uint32_t)((nrow * PADK + ke) * 2);
    }

    float acc[4][4][4];
#pragma unroll
    for (int mt = 0; mt < 4; mt++)
#pragma unroll
        for (int nt = 0; nt < 4; nt++)
#pragma unroll
            for (int r = 0; r < 4; r++) acc[mt][nt][r] = 0.0f;

    const int NCH = K >> 6;

    auto issue = [&](int ch, int st) {
        const int k0 = ch << 6;
        const uint32_t stg = sbase + (uint32_t)st * STAGE_B;
#pragma unroll
        for (int j = 0; j < 4; j++) {
            size_t offA = (size_t)(bm + crow[j]) * K + k0 + ccol[j];
            size_t offB = (size_t)(bn + crow[j]) * K + k0 + ccol[j];
            cp16(stg + cdst[j],              Ah_ + offA);
            cp16(stg + TILE_E * 2 + cdst[j], Bh_ + offB);
        }
    };

    issue(0, 0);
    asm volatile("cp.async.commit_group;" ::: "memory");

    for (int ch = 0; ch < NCH; ch++) {
        if (ch + 1 < NCH) issue(ch + 1, (ch + 1) & 1);
        asm volatile("cp.async.commit_group;" ::: "memory");
        asm volatile("cp.async.wait_group 1;" ::: "memory");
        __syncthreads();

        const uint32_t stg = sbase + (uint32_t)(ch & 1) * STAGE_B;

#pragma unroll
        for (int ks = 0; ks < 4; ks++) {
            const uint32_t kadd = (uint32_t)(ks << 5);
            uint32_t fah[4][4], fbh[2][4];
#pragma unroll
            for (int mt = 0; mt < 4; mt++)
                ldm4(fah[mt], stg + aoff[mt] + kadd);
#pragma unroll
            for (int np = 0; np < 2; np++)
                ldm4(fbh[np], stg + TILE_E * 2 + boff[np] + kadd);
#pragma unroll
            for (int mt = 0; mt < 4; mt++)
#pragma unroll
                for (int nt = 0; nt < 4; nt++)
                    MMA_F16(acc[mt][nt], fah[mt], &fbh[nt >> 1][(nt & 1) << 1]);
        }
        __syncthreads();
    }

    const int g = lane >> 2;
    const int t = lane & 3;

    if (MODE == 1) {
#pragma unroll
        for (int nt = 0; nt < 4; nt++) {
            int col = bn + wn * 32 + nt * 8 + t * 2;
            float b0v = bias[col], b1v = bias[col + 1];
#pragma unroll
            for (int mt = 0; mt < 4; mt++) {
                int row = bm + wm * 64 + mt * 16 + g;
                float2 lo2 = {acc[mt][nt][0] + b0v, acc[mt][nt][1] + b1v};
                float2 hi2 = {acc[mt][nt][2] + b0v, acc[mt][nt][3] + b1v};
                *(float2*)(C + (size_t)row * Nc + col)       = lo2;
                *(float2*)(C + (size_t)(row + 8) * Nc + col) = hi2;
            }
        }
    } else {
        const int sec = bn >> 10;              // 0=q, 1=k, 2=v (tile-uniform)
        const unsigned FULL = 0xffffffffu;
#pragma unroll
        for (int nt = 0; nt < 4; nt++) {
            const int col = bn + wn * 32 + nt * 8 + t * 2;
            const int cc  = col & 1023;
#pragma unroll
            for (int mt = 0; mt < 4; mt++) {
                int row = bm + wm * 64 + mt * 16 + g;
                float a0 = acc[mt][nt][0], a1 = acc[mt][nt][1];
                float a2 = acc[mt][nt][2], a3 = acc[mt][nt][3];
                size_t o0 = (size_t)row * DD + cc;
                size_t o1 = (size_t)(row + 8) * DD + cc;
                if (sec == 0) {
                    store_split(g_qh2, g_ql2, o0, a0 * SCALEF, a1 * SCALEF);
                    store_split(g_qh2, g_ql2, o1, a2 * SCALEF, a3 * SCALEF);
                } else if (sec == 1) {
                    store_split(g_kh2, g_kl2, o0, a0, a1);
                    store_split(g_kh2, g_kl2, o1, a2, a3);
                } else {
                    *(uint32_t*)(g_vf + o0) = pack2f16(a0, a1);
                    *(uint32_t*)(g_vf + o1) = pack2f16(a2, a3);
                }
            }
            // block-mean reduction for q/k (rows wm*64..+63 = one token block)
            if (sec < 2) {
                float s0 = 0.0f, s1 = 0.0f;
#pragma unroll
                for (int mt = 0; mt < 4; mt++) {
                    s0 += acc[mt][nt][0] + acc[mt][nt][2];
                    s1 += acc[mt][nt][1] + acc[mt][nt][3];
                }
                s0 += __shfl_xor_sync(FULL, s0, 4);
                s1 += __shfl_xor_sync(FULL, s1, 4);
                s0 += __shfl_xor_sync(FULL, s0, 8);
                s1 += __shfl_xor_sync(FULL, s1, 8);
                s0 += __shfl_xor_sync(FULL, s0, 16);
                s1 += __shfl_xor_sync(FULL, s1, 16);
                if (g == 0) {
                    int tb  = (bm + wm * 64) >> 6;       // global token block
                    int bb  = tb >> 5, mb = tb & 31;
                    int hh2 = cc >> 6, dd2 = cc & 63;
                    float* dst = (sec == 0) ? g_qb : g_kb;
                    float2 v2 = {s0 * (1.0f / 64), s1 * (1.0f / 64)};
                    *(float2*)(dst + (size_t)((bb * HH + hh2) * MM + mb) * HDD + dd2) = v2;
                }
            }
        }
    }
}

// =====================================================================
// Block scores + top-2 threshold + diagonal keep (8 warps/block)
// =====================================================================
__global__ __launch_bounds__(256) void mask_kernel()
{
    const int lane = threadIdx.x & 31;
    const int row  = blockIdx.x * 8 + (threadIdx.x >> 5);
    const int m    = row % MM;
    const int bh   = row / MM;

    const float* qb = g_qb + (size_t)row * HDD;
    const float* kb = g_kb + ((size_t)bh * MM + lane) * HDD;

    float s = 0.0f;
#pragma unroll
    for (int d4 = 0; d4 < 16; d4++) {
        float4 qv = *(const float4*)(qb + (d4 << 2));
        float4 kv = *(const float4*)(kb + (d4 << 2));
        s = fmaf(qv.x, kv.x, s); s = fmaf(qv.y, kv.y, s);
        s = fmaf(qv.z, kv.z, s); s = fmaf(qv.w, kv.w, s);
    }
    s *= SCALEF;

    const unsigned FULL = 0xffffffffu;
    float m1 = s;
#pragma unroll
    for (int off = 16; off; off >>= 1) m1 = fmaxf(m1, __shfl_xor_sync(FULL, m1, off));
    unsigned b1 = __ballot_sync(FULL, s == m1);
    int lead = __ffs(b1) - 1;
    float v2 = (lane == lead) ? -INFINITY : s;
    float m2 = v2;
#pragma unroll
    for (int off = 16; off; off >>= 1) m2 = fmaxf(m2, __shfl_xor_sync(FULL, m2, off));

    bool keep = (s >= m2) || (lane == m);
    unsigned km = __ballot_sync(FULL, keep);
    if (lane == 0) g_kcnt[row] = __popc(km);
    if (keep) {
        int pos = __popc(km & ((1u << lane) - 1u));
        g_kept[(size_t)row * MAXK + pos] = lane;
    }
}

// =====================================================================
// Sparse block attention on tensor cores, all-fp16 operands via
// cp.async, 2-stage K/V pipeline. (unchanged from R12)
// =====================================================================
#define APAD 72
#define ATQH 0u
#define ATQL 4608u
#define ATS0 9216u
#define ATSTG 13824u
#define ATT_SMEM 73728u

__global__ __launch_bounds__(128) void attn_kernel()
{
    extern __shared__ __align__(16) __half sma[];
    const uint32_t sb = smem_u32(sma);

    const int tid  = threadIdx.x;
    const int wid  = tid >> 5;
    const int lane = tid & 31;
    const int row  = blockIdx.x;
    const int m    = row % MM;
    const int h    = (row / MM) % HH;
    const int b    = row / (MM * HH);
    const int tok0 = b * NN + m * BSZ;
    const size_t hoff = (size_t)h * HDD;

    const int cnt = g_kcnt[row];
    const int* kept = g_kept + (size_t)row * MAXK;

    const int pr = tid >> 3;
    const int pc = (tid & 7) << 3;

    {
#pragma unroll
        for (int j = 0; j < 4; j++) {
            int r = pr + (j << 4);
            size_t g = (size_t)(tok0 + r) * DD + hoff + pc;
            uint32_t so = sb + (uint32_t)((r * APAD + pc) << 1);
            cp16(so + (ATQH << 1), g_qh2 + g);
            cp16(so + (ATQL << 1), g_ql2 + g);
        }
        const int kt = b * NN + kept[0] * BSZ;
#pragma unroll
        for (int j = 0; j < 4; j++) {
            int r = pr + (j << 4);
            size_t g = (size_t)(kt + r) * DD + hoff + pc;
            uint32_t so = sb + (uint32_t)((ATS0 + r * APAD + pc) << 1);
            cp16(so,                 g_kh2 + g);
            cp16(so + (4608u << 1),  g_kl2 + g);
            cp16(so + (9216u << 1),  g_vf  + g);
        }
        asm volatile("cp.async.commit_group;" ::: "memory");
    }

    uint32_t qab;
    {
        int mrow = wid * 16 + (lane & 15);
        qab = sb + (uint32_t)((mrow * APAD + ((lane >> 4) << 3)) << 1);
    }
    uint32_t kboff[4], voff[4];
#pragma unroll
    for (int np = 0; np < 4; np++) {
        int nrow = np * 16 + ((lane >> 4) << 3) + (lane & 7);
        int ke   = ((lane >> 3) & 1) << 3;
        kboff[np] = (uint32_t)((nrow * APAD + ke) << 1);
    }
#pragma unroll
    for (int dp = 0; dp < 4; dp++) {
        int vrow = (((lane >> 3) & 1) << 3) + (lane & 7);
        int vcol = dp * 16 + ((lane >> 4) << 3);
        voff[dp] = (uint32_t)((vrow * APAD + vcol) << 1);
    }

    uint32_t qh_a[4][4], ql_a[4][4];
    float c_o[8][4];
#pragma unroll
    for (int dt = 0; dt < 8; dt++)
#pragma unroll
        for (int r = 0; r < 4; r++) c_o[dt][r] = 0.0f;
    float mrun0 = -INFINITY, mrun1 = -INFINITY, lrun0 = 0.0f, lrun1 = 0.0f;

    for (int kbi = 0; kbi < cnt; kbi++) {
        if (kbi + 1 < cnt) {
            const int kt = b * NN + kept[kbi + 1] * BSZ;
            const uint32_t stb = ATS0 + (uint32_t)((kbi + 1) & 1) * ATSTG;
#pragma unroll
            for (int j = 0; j < 4; j++) {
                int r = pr + (j << 4);
                size_t g = (size_t)(kt + r) * DD + hoff + pc;
                uint32_t so = sb + (uint32_t)((stb + r * APAD + pc) << 1);
                cp16(so,                g_kh2 + g);
                cp16(so + (4608u << 1), g_kl2 + g);
                cp16(so + (9216u << 1), g_vf  + g);
            }
        }
        asm volatile("cp.async.commit_group;" ::: "memory");
        if (kbi + 1 < cnt)
            asm volatile("cp.async.wait_group 1;" ::: "memory");
        else
            asm volatile("cp.async.wait_group 0;" ::: "memory");
        __syncthreads();

        if (kbi == 0) {
#pragma unroll
            for (int ks = 0; ks < 4; ks++) {
                ldm4(qh_a[ks], qab + (ATQH << 1) + ks * 32);
                ldm4(ql_a[ks], qab + (ATQL << 1) + ks * 32);
            }
        }

        const uint32_t stg = sb + (uint32_t)((ATS0 + (uint32_t)(kbi & 1) * ATSTG) << 1);

        float c_s[8][4];
#pragma unroll
        for (int nt = 0; nt < 8; nt++)
#pragma unroll
            for (int r = 0; r < 4; r++) c_s[nt][r] = 0.0f;
#pragma unroll
        for (int ks = 0; ks < 4; ks++) {
            uint32_t kh[4][4], kl[4][4];
#pragma unroll
            for (int np = 0; np < 4; np++) {
                ldm4(kh[np], stg + kboff[np] + ks * 32);
                ldm4(kl[np], stg + (4608u << 1) + kboff[np] + ks * 32);
            }
#pragma unroll
            for (int nt = 0; nt < 8; nt++)
                MMA_F16(c_s[nt], qh_a[ks], &kh[nt >> 1][(nt & 1) << 1]);
#pragma unroll
            for (int nt = 0; nt < 8; nt++)
                MMA_F16(c_s[nt], qh_a[ks], &kl[nt >> 1][(nt & 1) << 1]);
#pragma unroll
            for (int nt = 0; nt < 8; nt++)
                MMA_F16(c_s[nt], ql_a[ks], &kh[nt >> 1][(nt & 1) << 1]);
        }

        const unsigned FULL = 0xffffffffu;
        float rmax0 = -INFINITY, rmax1 = -INFINITY;
#pragma unroll
        for (int nt = 0; nt < 8; nt++) {
            rmax0 = fmaxf(rmax0, fmaxf(c_s[nt][0], c_s[nt][1]));
            rmax1 = fmaxf(rmax1, fmaxf(c_s[nt][2], c_s[nt][3]));
        }
        rmax0 = fmaxf(rmax0, __shfl_xor_sync(FULL, rmax0, 1));
        rmax0 = fmaxf(rmax0, __shfl_xor_sync(FULL, rmax0, 2));
        rmax1 = fmaxf(rmax1, __shfl_xor_sync(FULL, rmax1, 1));
        rmax1 = fmaxf(rmax1, __shfl_xor_sync(FULL, rmax1, 2));

        float mn0 = fmaxf(mrun0, rmax0), mn1 = fmaxf(mrun1, rmax1);
        float e0 = __expf(mrun0 - mn0),  e1 = __expf(mrun1 - mn1);
        float rs0 = 0.0f, rs1 = 0.0f;
#pragma unroll
        for (int nt = 0; nt < 8; nt++) {
            c_s[nt][0] = __expf(c_s[nt][0] - mn0); rs0 += c_s[nt][0];
            c_s[nt][1] = __expf(c_s[nt][1] - mn0); rs0 += c_s[nt][1];
            c_s[nt][2] = __expf(c_s[nt][2] - mn1); rs1 += c_s[nt][2];
            c_s[nt][3] = __expf(c_s[nt][3] - mn1); rs1 += c_s[nt][3];
        }
        rs0 += __shfl_xor_sync(FULL, rs0, 1); rs0 += __shfl_xor_sync(FULL, rs0, 2);
        rs1 += __shfl_xor_sync(FULL, rs1, 1); rs1 += __shfl_xor_sync(FULL, rs1, 2);
        lrun0 = lrun0 * e0 + rs0;  lrun1 = lrun1 * e1 + rs1;
        mrun0 = mn0;               mrun1 = mn1;
#pragma unroll
        for (int dt = 0; dt < 8; dt++) {
            c_o[dt][0] *= e0; c_o[dt][1] *= e0;
            c_o[dt][2] *= e1; c_o[dt][3] *= e1;
        }

#pragma unroll
        for (int ks = 0; ks < 4; ks++) {
            uint32_t pA[4], pL[4];
#pragma unroll
            for (int half = 0; half < 2; half++) {
                const float* cs = c_s[2 * ks + half];
                float x0 = cs[0], x1 = cs[1], x2 = cs[2], x3 = cs[3];
                __half h0 = __float2half_rn(x0), h1 = __float2half_rn(x1);
                __half h2 = __float2half_rn(x2), h3 = __float2half_rn(x3);
                pA[2 * half]     = (uint32_t)__half_as_ushort(h0) |
                                   ((uint32_t)__half_as_ushort(h1) << 16);
                pA[2 * half + 1] = (uint32_t)__half_as_ushort(h2) |
                                   ((uint32_t)__half_as_ushort(h3) << 16);
                pL[2 * half]     = pack2f16(x0 - __half2float(h0),
                                            x1 - __half2float(h1));
                pL[2 * half + 1] = pack2f16(x2 - __half2float(h2),
                                            x3 - __half2float(h3));
            }
            uint32_t vf[4][4];
#pragma unroll
            for (int dp = 0; dp < 4; dp++)
                ldm4t(vf[dp], stg + (9216u << 1) + voff[dp]
                              + (uint32_t)(ks * 16 * APAD * 2));
#pragma unroll
            for (int dt = 0; dt < 8; dt++)
                MMA_F16(c_o[dt], pA, &vf[dt >> 1][(dt & 1) << 1]);
#pragma unroll
            for (int dt = 0; dt < 8; dt++)
                MMA_F16(c_o[dt], pL, &vf[dt >> 1][(dt & 1) << 1]);
        }
        __syncthreads();
    }

    const float inv0 = 1.0f / lrun0, inv1 = 1.0f / lrun1;
    const int g = lane >> 2, t = lane & 3;
    const int tk = tok0 + wid * 16 + g;
    const size_t o0 = (size_t)tk * DD + hoff;
    const size_t o1 = o0 + (size_t)8 * DD;
#pragma unroll
    for (int dt = 0; dt < 8; dt++) {
        int col = dt * 8 + t * 2;
        *(uint32_t*)(g_ah + o0 + col) = pack2f16(c_o[dt][0] * inv0, c_o[dt][1] * inv0);
        *(uint32_t*)(g_ah + o1 + col) = pack2f16(c_o[dt][2] * inv1, c_o[dt][3] * inv1);
    }
}

// =====================================================================
// Launch
// =====================================================================
extern "C" void kernel_launch(void* const* d_in, const int* in_sizes, int n_in,
                              void* d_out, int out_size)
{
    const float* x = nullptr; const float* qkv_w = nullptr;
    const float* proj_w = nullptr; const float* proj_b = nullptr;
    for (int i = 0; i < n_in; i++) {
        if      (in_sizes[i] == BB * NN * DD) x      = (const float*)d_in[i];
        else if (in_sizes[i] == 3 * DD * DD)  qkv_w  = (const float*)d_in[i];
        else if (in_sizes[i] == DD * DD)      proj_w = (const float*)d_in[i];
        else if (in_sizes[i] == DD)           proj_b = (const float*)d_in[i];
    }
    float* out = (float*)d_out;

    void* p;
    __half *xh, *wq, *wp, *ah;
    cudaGetSymbolAddress(&p, g_xh); xh = (__half*)p;
    cudaGetSymbolAddress(&p, g_wq); wq = (__half*)p;
    cudaGetSymbolAddress(&p, g_wp); wp = (__half*)p;
    cudaGetSymbolAddress(&p, g_ah); ah = (__half*)p;

    static int attr_done = 0;
    if (!attr_done) {
        cudaFuncSetAttribute(gemm_mma<0>, cudaFuncAttributeMaxDynamicSharedMemorySize, GEMM_SMEM);
        cudaFuncSetAttribute(gemm_mma<1>, cudaFuncAttributeMaxDynamicSharedMemorySize, GEMM_SMEM);
        cudaFuncSetAttribute(attn_kernel, cudaFuncAttributeMaxDynamicSharedMemorySize, ATT_SMEM);
        attr_done = 1;
    }

    {
        int n4 = N4_X + N4_WQ + N4_WP;
        split3_kernel<<<(n4 + 255) / 256, 256>>>(x, xh, qkv_w, wq, proj_w, wp);
    }
    gemm_mma<0><<<dim3(3 * DD / 128, TOK / 128), 256, GEMM_SMEM>>>(
        xh, wq, nullptr, nullptr, 3 * DD, DD);
    mask_kernel<<<BB * HH * MM / 8, 256>>>();
    attn_kernel<<<BB * HH * MM, 128, ATT_SMEM>>>();
    gemm_mma<1><<<dim3(DD / 128, TOK / 128), 256, GEMM_SMEM>>>(
        ah, wp, proj_b, out, DD, DD);
}

// round 14
// speedup vs baseline: 1.1198x; 1.0321x over previous
#include <cuda_runtime.h>
#include <cuda_fp16.h>
#include <math.h>
#include <stdint.h>

// Problem constants
#define BB   2
#define NN   2048
#define DD   1024
#define HH   16
#define HDD  64
#define BSZ  64
#define MM   32
#define SCALEF 0.125f
#define TOK  (BB * NN)

// ---------------- scratch ----------------
__device__ float g_qb  [BB * HH * MM * HDD];
__device__ float g_kb  [BB * HH * MM * HDD];
__device__ __half g_xh [TOK * DD];            // x fp16
__device__ __half g_wq [3 * DD * DD];         // weights fp16
__device__ __half g_wp [DD * DD];
__device__ __half g_ah [TOK * DD];            // attn out fp16
// attention operands produced by QKV epilogue:
__device__ __half g_qh2[TOK * DD], g_ql2[TOK * DD];   // q*0.125 hi/lo
__device__ __half g_kh2[TOK * DD], g_kl2[TOK * DD];   // k hi/lo
__device__ __half g_vf [TOK * DD];                    // v single

// =====================================================================
// helpers
// =====================================================================
static __device__ __forceinline__ uint32_t pack2f16(float a, float b) {
    return (uint32_t)__half_as_ushort(__float2half_rn(a)) |
           ((uint32_t)__half_as_ushort(__float2half_rn(b)) << 16);
}
static __device__ __forceinline__ uint32_t smem_u32(const void* p) {
    uint32_t a;
    asm("{ .reg .u64 t; cvta.to.shared.u64 t, %1; cvt.u32.u64 %0, t; }"
        : "=r"(a) : "l"(p));
    return a;
}
static __device__ __forceinline__ void cp16(uint32_t s, const void* g) {
    asm volatile("cp.async.cg.shared.global [%0], [%1], 16;"
                 :: "r"(s), "l"(g) : "memory");
}
static __device__ __forceinline__ void ldm4(uint32_t* r, uint32_t a) {
    asm volatile("ldmatrix.sync.aligned.m8n8.x4.shared.b16 {%0,%1,%2,%3}, [%4];"
        : "=r"(r[0]), "=r"(r[1]), "=r"(r[2]), "=r"(r[3]) : "r"(a));
}
static __device__ __forceinline__ void ldm4t(uint32_t* r, uint32_t a) {
    asm volatile("ldmatrix.sync.aligned.m8n8.x4.trans.shared.b16 {%0,%1,%2,%3}, [%4];"
        : "=r"(r[0]), "=r"(r[1]), "=r"(r[2]), "=r"(r[3]) : "r"(a));
}
static __device__ __forceinline__ void store_split(
    __half* hi, __half* lo, size_t off, float a, float b)
{
    __half ha = __float2half_rn(a), hb = __float2half_rn(b);
    *(uint32_t*)(hi + off) = (uint32_t)__half_as_ushort(ha) |
                             ((uint32_t)__half_as_ushort(hb) << 16);
    *(uint32_t*)(lo + off) = pack2f16(a - __half2float(ha), b - __half2float(hb));
}

#define MMA_F16(c, a, b)                                                   \
    asm volatile("mma.sync.aligned.m16n8k16.row.col.f32.f16.f16.f32 "      \
        "{%0,%1,%2,%3}, {%4,%5,%6,%7}, {%8,%9}, {%0,%1,%2,%3};"            \
        : "+f"((c)[0]), "+f"((c)[1]), "+f"((c)[2]), "+f"((c)[3])           \
        : "r"((a)[0]), "r"((a)[1]), "r"((a)[2]), "r"((a)[3]),              \
          "r"((b)[0]), "r"((b)[1]))

// =====================================================================
// fused fp32 -> fp16 convert for x, qkv_w, proj_w
// =====================================================================
#define N4_X (TOK * DD / 4)
#define N4_WQ (3 * DD * DD / 4)
#define N4_WP (DD * DD / 4)

__global__ __launch_bounds__(256) void split3_kernel(
    const float* __restrict__ sx, __half* __restrict__ xh,
    const float* __restrict__ sq, __half* __restrict__ wq,
    const float* __restrict__ sp, __half* __restrict__ wp)
{
    int i = blockIdx.x * blockDim.x + threadIdx.x;
    const float* src; __half* dst;
    if (i < N4_X) { src = sx; dst = xh; }
    else if (i < N4_X + N4_WQ) { i -= N4_X; src = sq; dst = wq; }
    else { i -= N4_X + N4_WQ; if (i >= N4_WP) return; src = sp; dst = wp; }
    float4 v = ((const float4*)src)[i];
    uint2 ph;
    ph.x = pack2f16(v.x, v.y); ph.y = pack2f16(v.z, v.w);
    ((uint2*)dst)[i] = ph;
}

// =====================================================================
// fp16 single-pass warp-MMA GEMM (NT).
// MODE 0 (QKV): epilogue writes fp16 attention operands + q/k block means.
// MODE 1 (proj): C = A*B + bias (fp32).
// =====================================================================
#define PADK 72
#define TILE_E (128 * PADK)
#define STAGE_B (2u * TILE_E * 2u)
#define GEMM_SMEM (2u * STAGE_B)

template <int MODE>
__global__ __launch_bounds__(256, 2) void gemm_mma(
    const __half* __restrict__ Ah_, const __half* __restrict__ Bh_,
    const float* __restrict__ bias, float* __restrict__ C,
    int Nc, int K)
{
    extern __shared__ __align__(16) uint16_t smg[];
    const uint32_t sbase = smem_u32(smg);

    const int tid  = threadIdx.x;
    const int wid  = tid >> 5;
    const int lane = tid & 31;
    const int wm   = wid & 1;
    const int wn   = wid >> 1;
    const int bm   = blockIdx.y * 128;
    const int bn   = blockIdx.x * 128;

    int crow[4]; uint32_t cdst[4]; int ccol[4];
#pragma unroll
    for (int j = 0; j < 4; j++) {
        int lin = tid + (j << 8);
        crow[j] = lin >> 3;
        ccol[j] = (lin & 7) << 3;
        cdst[j] = (uint32_t)(crow[j] * PADK * 2 + (lin & 7) * 16);
    }

    uint32_t aoff[4];
#pragma unroll
    for (int mt = 0; mt < 4; mt++) {
        int mrow = wm * 64 + mt * 16 + (lane & 15);
        int ke   = (lane >> 4) << 3;
        aoff[mt] = (uint32_t)((mrow * PADK + ke) * 2);
    }
    uint32_t boff[2];
#pragma unroll
    for (int np = 0; np < 2; np++) {
        int nrow = wn * 32 + np * 16 + ((lane >> 4) << 3) + (lane & 7);
        int ke   = ((lane >> 3) & 1) << 3;
        boff[np] = (uint32_t)((nrow * PADK + ke) * 2);
    }

    float acc[4][4][4];
#pragma unroll
    for (int mt = 0; mt < 4; mt++)
#pragma unroll
        for (int nt = 0; nt < 4; nt++)
#pragma unroll
            for (int r = 0; r < 4; r++) acc[mt][nt][r] = 0.0f;

    const int NCH = K >> 6;

    auto issue = [&](int ch, int st) {
        const int k0 = ch << 6;
        const uint32_t stg = sbase + (uint32_t)st * STAGE_B;
#pragma unroll
        for (int j = 0; j < 4; j++) {
            size_t offA = (size_t)(bm + crow[j]) * K + k0 + ccol[j];
            size_t offB = (size_t)(bn + crow[j]) * K + k0 + ccol[j];
            cp16(stg + cdst[j],              Ah_ + offA);
            cp16(stg + TILE_E * 2 + cdst[j], Bh_ + offB);
        }
    };

    issue(0, 0);
    asm volatile("cp.async.commit_group;" ::: "memory");

    for (int ch = 0; ch < NCH; ch++) {
        if (ch + 1 < NCH) issue(ch + 1, (ch + 1) & 1);
        asm volatile("cp.async.commit_group;" ::: "memory");
        asm volatile("cp.async.wait_group 1;" ::: "memory");
        __syncthreads();

        const uint32_t stg = sbase + (uint32_t)(ch & 1) * STAGE_B;

#pragma unroll
        for (int ks = 0; ks < 4; ks++) {
            const uint32_t kadd = (uint32_t)(ks << 5);
            uint32_t fah[4][4], fbh[2][4];
#pragma unroll
            for (int mt = 0; mt < 4; mt++)
                ldm4(fah[mt], stg + aoff[mt] + kadd);
#pragma unroll
            for (int np = 0; np < 2; np++)
                ldm4(fbh[np], stg + TILE_E * 2 + boff[np] + kadd);
#pragma unroll
            for (int mt = 0; mt < 4; mt++)
#pragma unroll
                for (int nt = 0; nt < 4; nt++)
                    MMA_F16(acc[mt][nt], fah[mt], &fbh[nt >> 1][(nt & 1) << 1]);
        }
        __syncthreads();
    }

    const int g = lane >> 2;
    const int t = lane & 3;

    if (MODE == 1) {
#pragma unroll
        for (int nt = 0; nt < 4; nt++) {
            int col = bn + wn * 32 + nt * 8 + t * 2;
            float b0v = bias[col], b1v = bias[col + 1];
#pragma unroll
            for (int mt = 0; mt < 4; mt++) {
                int row = bm + wm * 64 + mt * 16 + g;
                float2 lo2 = {acc[mt][nt][0] + b0v, acc[mt][nt][1] + b1v};
                float2 hi2 = {acc[mt][nt][2] + b0v, acc[mt][nt][3] + b1v};
                *(float2*)(C + (size_t)row * Nc + col)       = lo2;
                *(float2*)(C + (size_t)(row + 8) * Nc + col) = hi2;
            }
        }
    } else {
        const int sec = bn >> 10;              // 0=q, 1=k, 2=v (tile-uniform)
        const unsigned FULL = 0xffffffffu;
#pragma unroll
        for (int nt = 0; nt < 4; nt++) {
            const int col = bn + wn * 32 + nt * 8 + t * 2;
            const int cc  = col & 1023;
#pragma unroll
            for (int mt = 0; mt < 4; mt++) {
                int row = bm + wm * 64 + mt * 16 + g;
                float a0 = acc[mt][nt][0], a1 = acc[mt][nt][1];
                float a2 = acc[mt][nt][2], a3 = acc[mt][nt][3];
                size_t o0 = (size_t)row * DD + cc;
                size_t o1 = (size_t)(row + 8) * DD + cc;
                if (sec == 0) {
                    store_split(g_qh2, g_ql2, o0, a0 * SCALEF, a1 * SCALEF);
                    store_split(g_qh2, g_ql2, o1, a2 * SCALEF, a3 * SCALEF);
                } else if (sec == 1) {
                    store_split(g_kh2, g_kl2, o0, a0, a1);
                    store_split(g_kh2, g_kl2, o1, a2, a3);
                } else {
                    *(uint32_t*)(g_vf + o0) = pack2f16(a0, a1);
                    *(uint32_t*)(g_vf + o1) = pack2f16(a2, a3);
                }
            }
            if (sec < 2) {
                float s0 = 0.0f, s1 = 0.0f;
#pragma unroll
                for (int mt = 0; mt < 4; mt++) {
                    s0 += acc[mt][nt][0] + acc[mt][nt][2];
                    s1 += acc[mt][nt][1] + acc[mt][nt][3];
                }
                s0 += __shfl_xor_sync(FULL, s0, 4);
                s1 += __shfl_xor_sync(FULL, s1, 4);
                s0 += __shfl_xor_sync(FULL, s0, 8);
                s1 += __shfl_xor_sync(FULL, s1, 8);
                s0 += __shfl_xor_sync(FULL, s0, 16);
                s1 += __shfl_xor_sync(FULL, s1, 16);
                if (g == 0) {
                    int tb  = (bm + wm * 64) >> 6;
                    int bb  = tb >> 5, mb = tb & 31;
                    int hh2 = cc >> 6, dd2 = cc & 63;
                    float* dst = (sec == 0) ? g_qb : g_kb;
                    float2 v2 = {s0 * (1.0f / 64), s1 * (1.0f / 64)};
                    *(float2*)(dst + (size_t)((bb * HH + hh2) * MM + mb) * HDD + dd2) = v2;
                }
            }
        }
    }
}

// =====================================================================
// Sparse block attention on tensor cores with FUSED top-2 block mask.
// Warp 0 computes the row's kept-block list while Q cp.async is in
// flight; all-fp16 operands; 2-stage K/V pipeline.
// =====================================================================
#define APAD 72
#define ATQH 0u
#define ATQL 4608u
#define ATS0 9216u
#define ATSTG 13824u
#define ATT_SMEM 73728u

__global__ __launch_bounds__(128) void attn_kernel()
{
    extern __shared__ __align__(16) __half sma[];
    __shared__ int s_kept[32];
    __shared__ int s_cnt;
    const uint32_t sb = smem_u32(sma);

    const int tid  = threadIdx.x;
    const int wid  = tid >> 5;
    const int lane = tid & 31;
    const int row  = blockIdx.x;
    const int m    = row % MM;
    const int h    = (row / MM) % HH;
    const int b    = row / (MM * HH);
    const int tok0 = b * NN + m * BSZ;
    const size_t hoff = (size_t)h * HDD;

    const int pr = tid >> 3;
    const int pc = (tid & 7) << 3;

    // ---- group A: Q hi/lo loads (mask does not need them) ----
#pragma unroll
    for (int j = 0; j < 4; j++) {
        int r = pr + (j << 4);
        size_t g = (size_t)(tok0 + r) * DD + hoff + pc;
        uint32_t so = sb + (uint32_t)((r * APAD + pc) << 1);
        cp16(so + (ATQH << 1), g_qh2 + g);
        cp16(so + (ATQL << 1), g_ql2 + g);
    }
    asm volatile("cp.async.commit_group;" ::: "memory");

    // ---- fused mask: warp 0 computes top-2 kept blocks for this row ----
    if (wid == 0) {
        const float* qbv = g_qb + (size_t)row * HDD;
        const float* kbv = g_kb + ((size_t)(row / MM) * MM + lane) * HDD;
        float s = 0.0f;
#pragma unroll
        for (int d4 = 0; d4 < 16; d4++) {
            float4 qv = *(const float4*)(qbv + (d4 << 2));
            float4 kv = *(const float4*)(kbv + (d4 << 2));
            s = fmaf(qv.x, kv.x, s); s = fmaf(qv.y, kv.y, s);
            s = fmaf(qv.z, kv.z, s); s = fmaf(qv.w, kv.w, s);
        }
        s *= SCALEF;
        const unsigned FULL = 0xffffffffu;
        float m1 = s;
#pragma unroll
        for (int off = 16; off; off >>= 1) m1 = fmaxf(m1, __shfl_xor_sync(FULL, m1, off));
        unsigned b1 = __ballot_sync(FULL, s == m1);
        int lead = __ffs(b1) - 1;
        float v2 = (lane == lead) ? -INFINITY : s;
        float m2 = v2;
#pragma unroll
        for (int off = 16; off; off >>= 1) m2 = fmaxf(m2, __shfl_xor_sync(FULL, m2, off));
        bool keep = (s >= m2) || (lane == m);
        unsigned km = __ballot_sync(FULL, keep);
        if (lane == 0) s_cnt = __popc(km);
        if (keep) {
            int pos = __popc(km & ((1u << lane) - 1u));
            s_kept[pos] = lane;
        }
    }
    __syncthreads();
    const int cnt = s_cnt;

    // ---- group B: tile 0 prefetch ----
    {
        const int kt = b * NN + s_kept[0] * BSZ;
#pragma unroll
        for (int j = 0; j < 4; j++) {
            int r = pr + (j << 4);
            size_t g = (size_t)(kt + r) * DD + hoff + pc;
            uint32_t so = sb + (uint32_t)((ATS0 + r * APAD + pc) << 1);
            cp16(so,                 g_kh2 + g);
            cp16(so + (4608u << 1),  g_kl2 + g);
            cp16(so + (9216u << 1),  g_vf  + g);
        }
        asm volatile("cp.async.commit_group;" ::: "memory");
    }

    uint32_t qab;
    {
        int mrow = wid * 16 + (lane & 15);
        qab = sb + (uint32_t)((mrow * APAD + ((lane >> 4) << 3)) << 1);
    }
    uint32_t kboff[4], voff[4];
#pragma unroll
    for (int np = 0; np < 4; np++) {
        int nrow = np * 16 + ((lane >> 4) << 3) + (lane & 7);
        int ke   = ((lane >> 3) & 1) << 3;
        kboff[np] = (uint32_t)((nrow * APAD + ke) << 1);
    }
#pragma unroll
    for (int dp = 0; dp < 4; dp++) {
        int vrow = (((lane >> 3) & 1) << 3) + (lane & 7);
        int vcol = dp * 16 + ((lane >> 4) << 3);
        voff[dp] = (uint32_t)((vrow * APAD + vcol) << 1);
    }

    uint32_t qh_a[4][4], ql_a[4][4];
    float c_o[8][4];
#pragma unroll
    for (int dt = 0; dt < 8; dt++)
#pragma unroll
        for (int r = 0; r < 4; r++) c_o[dt][r] = 0.0f;
    float mrun0 = -INFINITY, mrun1 = -INFINITY, lrun0 = 0.0f, lrun1 = 0.0f;

    for (int kbi = 0; kbi < cnt; kbi++) {
        if (kbi + 1 < cnt) {
            const int kt = b * NN + s_kept[kbi + 1] * BSZ;
            const uint32_t stb = ATS0 + (uint32_t)((kbi + 1) & 1) * ATSTG;
#pragma unroll
            for (int j = 0; j < 4; j++) {
                int r = pr + (j << 4);
                size_t g = (size_t)(kt + r) * DD + hoff + pc;
                uint32_t so = sb + (uint32_t)((stb + r * APAD + pc) << 1);
                cp16(so,                g_kh2 + g);
                cp16(so + (4608u << 1), g_kl2 + g);
                cp16(so + (9216u << 1), g_vf  + g);
            }
        }
        asm volatile("cp.async.commit_group;" ::: "memory");
        if (kbi + 1 < cnt)
            asm volatile("cp.async.wait_group 1;" ::: "memory");
        else
            asm volatile("cp.async.wait_group 0;" ::: "memory");
        __syncthreads();

        if (kbi == 0) {
#pragma unroll
            for (int ks = 0; ks < 4; ks++) {
                ldm4(qh_a[ks], qab + (ATQH << 1) + ks * 32);
                ldm4(ql_a[ks], qab + (ATQL << 1) + ks * 32);
            }
        }

        const uint32_t stg = sb + (uint32_t)((ATS0 + (uint32_t)(kbi & 1) * ATSTG) << 1);

        float c_s[8][4];
#pragma unroll
        for (int nt = 0; nt < 8; nt++)
#pragma unroll
            for (int r = 0; r < 4; r++) c_s[nt][r] = 0.0f;
#pragma unroll
        for (int ks = 0; ks < 4; ks++) {
            uint32_t kh[4][4], kl[4][4];
#pragma unroll
            for (int np = 0; np < 4; np++) {
                ldm4(kh[np], stg + kboff[np] + ks * 32);
                ldm4(kl[np], stg + (4608u << 1) + kboff[np] + ks * 32);
            }
#pragma unroll
            for (int nt = 0; nt < 8; nt++)
                MMA_F16(c_s[nt], qh_a[ks], &kh[nt >> 1][(nt & 1) << 1]);
#pragma unroll
            for (int nt = 0; nt < 8; nt++)
                MMA_F16(c_s[nt], qh_a[ks], &kl[nt >> 1][(nt & 1) << 1]);
#pragma unroll
            for (int nt = 0; nt < 8; nt++)
                MMA_F16(c_s[nt], ql_a[ks], &kh[nt >> 1][(nt & 1) << 1]);
        }

        const unsigned FULL = 0xffffffffu;
        float rmax0 = -INFINITY, rmax1 = -INFINITY;
#pragma unroll
        for (int nt = 0; nt < 8; nt++) {
            rmax0 = fmaxf(rmax0, fmaxf(c_s[nt][0], c_s[nt][1]));
            rmax1 = fmaxf(rmax1, fmaxf(c_s[nt][2], c_s[nt][3]));
        }
        rmax0 = fmaxf(rmax0, __shfl_xor_sync(FULL, rmax0, 1));
        rmax0 = fmaxf(rmax0, __shfl_xor_sync(FULL, rmax0, 2));
        rmax1 = fmaxf(rmax1, __shfl_xor_sync(FULL, rmax1, 1));
        rmax1 = fmaxf(rmax1, __shfl_xor_sync(FULL, rmax1, 2));

        float mn0 = fmaxf(mrun0, rmax0), mn1 = fmaxf(mrun1, rmax1);
        float e0 = __expf(mrun0 - mn0),  e1 = __expf(mrun1 - mn1);
        float rs0 = 0.0f, rs1 = 0.0f;
#pragma unroll
        for (int nt = 0; nt < 8; nt++) {
            c_s[nt][0] = __expf(c_s[nt][0] - mn0); rs0 += c_s[nt][0];
            c_s[nt][1] = __expf(c_s[nt][1] - mn0); rs0 += c_s[nt][1];
            c_s[nt][2] = __expf(c_s[nt][2] - mn1); rs1 += c_s[nt][2];
            c_s[nt][3] = __expf(c_s[nt][3] - mn1); rs1 += c_s[nt][3];
        }
        rs0 += __shfl_xor_sync(FULL, rs0, 1); rs0 += __shfl_xor_sync(FULL, rs0, 2);
        rs1 += __shfl_xor_sync(FULL, rs1, 1); rs1 += __shfl_xor_sync(FULL, rs1, 2);
        lrun0 = lrun0 * e0 + rs0;  lrun1 = lrun1 * e1 + rs1;
        mrun0 = mn0;               mrun1 = mn1;
#pragma unroll
        for (int dt = 0; dt < 8; dt++) {
            c_o[dt][0] *= e0; c_o[dt][1] *= e0;
            c_o[dt][2] *= e1; c_o[dt][3] *= e1;
        }

#pragma unroll
        for (int ks = 0; ks < 4; ks++) {
            uint32_t pA[4], pL[4];
#pragma unroll
            for (int half = 0; half < 2; half++) {
                const float* cs = c_s[2 * ks + half];
                float x0 = cs[0], x1 = cs[1], x2 = cs[2], x3 = cs[3];
                __half h0 = __float2half_rn(x0), h1 = __float2half_rn(x1);
                __half h2 = __float2half_rn(x2), h3 = __float2half_rn(x3);
                pA[2 * half]     = (uint32_t)__half_as_ushort(h0) |
                                   ((uint32_t)__half_as_ushort(h1) << 16);
                pA[2 * half + 1] = (uint32_t)__half_as_ushort(h2) |
                                   ((uint32_t)__half_as_ushort(h3) << 16);
                pL[2 * half]     = pack2f16(x0 - __half2float(h0),
                                            x1 - __half2float(h1));
                pL[2 * half + 1] = pack2f16(x2 - __half2float(h2),
                                            x3 - __half2float(h3));
            }
            uint32_t vf[4][4];
#pragma unroll
            for (int dp = 0; dp < 4; dp++)
                ldm4t(vf[dp], stg + (9216u << 1) + voff[dp]
                              + (uint32_t)(ks * 16 * APAD * 2));
#pragma unroll
            for (int dt = 0; dt < 8; dt++)
                MMA_F16(c_o[dt], pA, &vf[dt >> 1][(dt & 1) << 1]);
#pragma unroll
            for (int dt = 0; dt < 8; dt++)
                MMA_F16(c_o[dt], pL, &vf[dt >> 1][(dt & 1) << 1]);
        }
        __syncthreads();
    }

    const float inv0 = 1.0f / lrun0, inv1 = 1.0f / lrun1;
    const int g = lane >> 2, t = lane & 3;
    const int tk = tok0 + wid * 16 + g;
    const size_t o0 = (size_t)tk * DD + hoff;
    const size_t o1 = o0 + (size_t)8 * DD;
#pragma unroll
    for (int dt = 0; dt < 8; dt++) {
        int col = dt * 8 + t * 2;
        *(uint32_t*)(g_ah + o0 + col) = pack2f16(c_o[dt][0] * inv0, c_o[dt][1] * inv0);
        *(uint32_t*)(g_ah + o1 + col) = pack2f16(c_o[dt][2] * inv1, c_o[dt][3] * inv1);
    }
}

// =====================================================================
// Launch
// =====================================================================
extern "C" void kernel_launch(void* const* d_in, const int* in_sizes, int n_in,
                              void* d_out, int out_size)
{
    const float* x = nullptr; const float* qkv_w = nullptr;
    const float* proj_w = nullptr; const float* proj_b = nullptr;
    for (int i = 0; i < n_in; i++) {
        if      (in_sizes[i] == BB * NN * DD) x      = (const float*)d_in[i];
        else if (in_sizes[i] == 3 * DD * DD)  qkv_w  = (const float*)d_in[i];
        else if (in_sizes[i] == DD * DD)      proj_w = (const float*)d_in[i];
        else if (in_sizes[i] == DD)           proj_b = (const float*)d_in[i];
    }
    float* out = (float*)d_out;

    void* p;
    __half *xh, *wq, *wp, *ah;
    cudaGetSymbolAddress(&p, g_xh); xh = (__half*)p;
    cudaGetSymbolAddress(&p, g_wq); wq = (__half*)p;
    cudaGetSymbolAddress(&p, g_wp); wp = (__half*)p;
    cudaGetSymbolAddress(&p, g_ah); ah = (__half*)p;

    static int attr_done = 0;
    if (!attr_done) {
        cudaFuncSetAttribute(gemm_mma<0>, cudaFuncAttributeMaxDynamicSharedMemorySize, GEMM_SMEM);
        cudaFuncSetAttribute(gemm_mma<1>, cudaFuncAttributeMaxDynamicSharedMemorySize, GEMM_SMEM);
        cudaFuncSetAttribute(attn_kernel, cudaFuncAttributeMaxDynamicSharedMemorySize, ATT_SMEM);
        attr_done = 1;
    }

    {
        int n4 = N4_X + N4_WQ + N4_WP;
        split3_kernel<<<(n4 + 255) / 256, 256>>>(x, xh, qkv_w, wq, proj_w, wp);
    }
    gemm_mma<0><<<dim3(3 * DD / 128, TOK / 128), 256, GEMM_SMEM>>>(
        xh, wq, nullptr, nullptr, 3 * DD, DD);
    attn_kernel<<<BB * HH * MM, 128, ATT_SMEM>>>();
    gemm_mma<1><<<dim3(DD / 128, TOK / 128), 256, GEMM_SMEM>>>(
        ah, wp, proj_b, out, DD, DD);
}

// round 15
// speedup vs baseline: 1.1295x; 1.0087x over previous
#include <cuda_runtime.h>
#include <cuda_fp16.h>
#include <math.h>
#include <stdint.h>

// Problem constants
#define BB   2
#define NN   2048
#define DD   1024
#define HH   16
#define HDD  64
#define BSZ  64
#define MM   32
#define SCALEF 0.125f
#define TOK  (BB * NN)

// ---------------- scratch ----------------
__device__ float g_qb  [BB * HH * MM * HDD];
__device__ float g_kb  [BB * HH * MM * HDD];
__device__ __half g_xh [TOK * DD];
__device__ __half g_wq [3 * DD * DD];
__device__ __half g_wp [DD * DD];
__device__ __half g_ah [TOK * DD];
__device__ __half g_qh2[TOK * DD], g_ql2[TOK * DD];
__device__ __half g_kh2[TOK * DD], g_kl2[TOK * DD];
__device__ __half g_vf [TOK * DD];

// =====================================================================
// helpers
// =====================================================================
static __device__ __forceinline__ uint32_t pack2f16(float a, float b) {
    return (uint32_t)__half_as_ushort(__float2half_rn(a)) |
           ((uint32_t)__half_as_ushort(__float2half_rn(b)) << 16);
}
static __device__ __forceinline__ uint32_t smem_u32(const void* p) {
    uint32_t a;
    asm("{ .reg .u64 t; cvta.to.shared.u64 t, %1; cvt.u32.u64 %0, t; }"
        : "=r"(a) : "l"(p));
    return a;
}
static __device__ __forceinline__ void cp16(uint32_t s, const void* g) {
    asm volatile("cp.async.cg.shared.global [%0], [%1], 16;"
                 :: "r"(s), "l"(g) : "memory");
}
static __device__ __forceinline__ void ldm4(uint32_t* r, uint32_t a) {
    asm volatile("ldmatrix.sync.aligned.m8n8.x4.shared.b16 {%0,%1,%2,%3}, [%4];"
        : "=r"(r[0]), "=r"(r[1]), "=r"(r[2]), "=r"(r[3]) : "r"(a));
}
static __device__ __forceinline__ void ldm4t(uint32_t* r, uint32_t a) {
    asm volatile("ldmatrix.sync.aligned.m8n8.x4.trans.shared.b16 {%0,%1,%2,%3}, [%4];"
        : "=r"(r[0]), "=r"(r[1]), "=r"(r[2]), "=r"(r[3]) : "r"(a));
}
static __device__ __forceinline__ void store_split(
    __half* hi, __half* lo, size_t off, float a, float b)
{
    __half ha = __float2half_rn(a), hb = __float2half_rn(b);
    *(uint32_t*)(hi + off) = (uint32_t)__half_as_ushort(ha) |
                             ((uint32_t)__half_as_ushort(hb) << 16);
    *(uint32_t*)(lo + off) = pack2f16(a - __half2float(ha), b - __half2float(hb));
}

#define MMA_F16(c, a, b)                                                   \
    asm volatile("mma.sync.aligned.m16n8k16.row.col.f32.f16.f16.f32 "      \
        "{%0,%1,%2,%3}, {%4,%5,%6,%7}, {%8,%9}, {%0,%1,%2,%3};"            \
        : "+f"((c)[0]), "+f"((c)[1]), "+f"((c)[2]), "+f"((c)[3])           \
        : "r"((a)[0]), "r"((a)[1]), "r"((a)[2]), "r"((a)[3]),              \
          "r"((b)[0]), "r"((b)[1]))

// =====================================================================
// fused fp32 -> fp16 convert for x, qkv_w, proj_w
// =====================================================================
#define N4_X (TOK * DD / 4)
#define N4_WQ (3 * DD * DD / 4)
#define N4_WP (DD * DD / 4)

__global__ __launch_bounds__(256) void split3_kernel(
    const float* __restrict__ sx, __half* __restrict__ xh,
    const float* __restrict__ sq, __half* __restrict__ wq,
    const float* __restrict__ sp, __half* __restrict__ wp)
{
    int i = blockIdx.x * blockDim.x + threadIdx.x;
    const float* src; __half* dst;
    if (i < N4_X) { src = sx; dst = xh; }
    else if (i < N4_X + N4_WQ) { i -= N4_X; src = sq; dst = wq; }
    else { i -= N4_X + N4_WQ; if (i >= N4_WP) return; src = sp; dst = wp; }
    float4 v = ((const float4*)src)[i];
    uint2 ph;
    ph.x = pack2f16(v.x, v.y); ph.y = pack2f16(v.z, v.w);
    ((uint2*)dst)[i] = ph;
}

// =====================================================================
// fp16 single-pass warp-MMA GEMM (NT).  (unchanged from R14)
// =====================================================================
#define PADK 72
#define TILE_E (128 * PADK)
#define STAGE_B (2u * TILE_E * 2u)
#define GEMM_SMEM (2u * STAGE_B)

template <int MODE>
__global__ __launch_bounds__(256, 2) void gemm_mma(
    const __half* __restrict__ Ah_, const __half* __restrict__ Bh_,
    const float* __restrict__ bias, float* __restrict__ C,
    int Nc, int K)
{
    extern __shared__ __align__(16) uint16_t smg[];
    const uint32_t sbase = smem_u32(smg);

    const int tid  = threadIdx.x;
    const int wid  = tid >> 5;
    const int lane = tid & 31;
    const int wm   = wid & 1;
    const int wn   = wid >> 1;
    const int bm   = blockIdx.y * 128;
    const int bn   = blockIdx.x * 128;

    int crow[4]; uint32_t cdst[4]; int ccol[4];
#pragma unroll
    for (int j = 0; j < 4; j++) {
        int lin = tid + (j << 8);
        crow[j] = lin >> 3;
        ccol[j] = (lin & 7) << 3;
        cdst[j] = (uint32_t)(crow[j] * PADK * 2 + (lin & 7) * 16);
    }

    uint32_t aoff[4];
#pragma unroll
    for (int mt = 0; mt < 4; mt++) {
        int mrow = wm * 64 + mt * 16 + (lane & 15);
        int ke   = (lane >> 4) << 3;
        aoff[mt] = (uint32_t)((mrow * PADK + ke) * 2);
    }
    uint32_t boff[2];
#pragma unroll
    for (int np = 0; np < 2; np++) {
        int nrow = wn * 32 + np * 16 + ((lane >> 4) << 3) + (lane & 7);
        int ke   = ((lane >> 3) & 1) << 3;
        boff[np] = (uint32_t)((nrow * PADK + ke) * 2);
    }

    float acc[4][4][4];
#pragma unroll
    for (int mt = 0; mt < 4; mt++)
#pragma unroll
        for (int nt = 0; nt < 4; nt++)
#pragma unroll
            for (int r = 0; r < 4; r++) acc[mt][nt][r] = 0.0f;

    const int NCH = K >> 6;

    auto issue = [&](int ch, int st) {
        const int k0 = ch << 6;
        const uint32_t stg = sbase + (uint32_t)st * STAGE_B;
#pragma unroll
        for (int j = 0; j < 4; j++) {
            size_t offA = (size_t)(bm + crow[j]) * K + k0 + ccol[j];
            size_t offB = (size_t)(bn + crow[j]) * K + k0 + ccol[j];
            cp16(stg + cdst[j],              Ah_ + offA);
            cp16(stg + TILE_E * 2 + cdst[j], Bh_ + offB);
        }
    };

    issue(0, 0);
    asm volatile("cp.async.commit_group;" ::: "memory");

    for (int ch = 0; ch < NCH; ch++) {
        if (ch + 1 < NCH) issue(ch + 1, (ch + 1) & 1);
        asm volatile("cp.async.commit_group;" ::: "memory");
        asm volatile("cp.async.wait_group 1;" ::: "memory");
        __syncthreads();

        const uint32_t stg = sbase + (uint32_t)(ch & 1) * STAGE_B;

#pragma unroll
        for (int ks = 0; ks < 4; ks++) {
            const uint32_t kadd = (uint32_t)(ks << 5);
            uint32_t fah[4][4], fbh[2][4];
#pragma unroll
            for (int mt = 0; mt < 4; mt++)
                ldm4(fah[mt], stg + aoff[mt] + kadd);
#pragma unroll
            for (int np = 0; np < 2; np++)
                ldm4(fbh[np], stg + TILE_E * 2 + boff[np] + kadd);
#pragma unroll
            for (int mt = 0; mt < 4; mt++)
#pragma unroll
                for (int nt = 0; nt < 4; nt++)
                    MMA_F16(acc[mt][nt], fah[mt], &fbh[nt >> 1][(nt & 1) << 1]);
        }
        __syncthreads();
    }

    const int g = lane >> 2;
    const int t = lane & 3;

    if (MODE == 1) {
#pragma unroll
        for (int nt = 0; nt < 4; nt++) {
            int col = bn + wn * 32 + nt * 8 + t * 2;
            float b0v = bias[col], b1v = bias[col + 1];
#pragma unroll
            for (int mt = 0; mt < 4; mt++) {
                int row = bm + wm * 64 + mt * 16 + g;
                float2 lo2 = {acc[mt][nt][0] + b0v, acc[mt][nt][1] + b1v};
                float2 hi2 = {acc[mt][nt][2] + b0v, acc[mt][nt][3] + b1v};
                *(float2*)(C + (size_t)row * Nc + col)       = lo2;
                *(float2*)(C + (size_t)(row + 8) * Nc + col) = hi2;
            }
        }
    } else {
        const int sec = bn >> 10;
        const unsigned FULL = 0xffffffffu;
#pragma unroll
        for (int nt = 0; nt < 4; nt++) {
            const int col = bn + wn * 32 + nt * 8 + t * 2;
            const int cc  = col & 1023;
#pragma unroll
            for (int mt = 0; mt < 4; mt++) {
                int row = bm + wm * 64 + mt * 16 + g;
                float a0 = acc[mt][nt][0], a1 = acc[mt][nt][1];
                float a2 = acc[mt][nt][2], a3 = acc[mt][nt][3];
                size_t o0 = (size_t)row * DD + cc;
                size_t o1 = (size_t)(row + 8) * DD + cc;
                if (sec == 0) {
                    store_split(g_qh2, g_ql2, o0, a0 * SCALEF, a1 * SCALEF);
                    store_split(g_qh2, g_ql2, o1, a2 * SCALEF, a3 * SCALEF);
                } else if (sec == 1) {
                    store_split(g_kh2, g_kl2, o0, a0, a1);
                    store_split(g_kh2, g_kl2, o1, a2, a3);
                } else {
                    *(uint32_t*)(g_vf + o0) = pack2f16(a0, a1);
                    *(uint32_t*)(g_vf + o1) = pack2f16(a2, a3);
                }
            }
            if (sec < 2) {
                float s0 = 0.0f, s1 = 0.0f;
#pragma unroll
                for (int mt = 0; mt < 4; mt++) {
                    s0 += acc[mt][nt][0] + acc[mt][nt][2];
                    s1 += acc[mt][nt][1] + acc[mt][nt][3];
                }
                s0 += __shfl_xor_sync(FULL, s0, 4);
                s1 += __shfl_xor_sync(FULL, s1, 4);
                s0 += __shfl_xor_sync(FULL, s0, 8);
                s1 += __shfl_xor_sync(FULL, s1, 8);
                s0 += __shfl_xor_sync(FULL, s0, 16);
                s1 += __shfl_xor_sync(FULL, s1, 16);
                if (g == 0) {
                    int tb  = (bm + wm * 64) >> 6;
                    int bb  = tb >> 5, mb = tb & 31;
                    int hh2 = cc >> 6, dd2 = cc & 63;
                    float* dst = (sec == 0) ? g_qb : g_kb;
                    float2 v2 = {s0 * (1.0f / 64), s1 * (1.0f / 64)};
                    *(float2*)(dst + (size_t)((bb * HH + hh2) * MM + mb) * HDD + dd2) = v2;
                }
            }
        }
    }
}

// =====================================================================
// Sparse block attention, fused mask, smem OVERLAY:
//   region [0,13824)  = stage1 (Q hi/lo lives here until fragments
//                       are register-resident, then reused)
//   region [13824,27648) = stage0
// 55.3 KB dyn smem, __launch_bounds__(128,4) -> 4 CTAs/SM.
// =====================================================================
#define APAD 72
#define ATQH 0u
#define ATQL 4608u
#define ATSTG 13824u
#define ATT_SMEM 55296u

__global__ __launch_bounds__(128, 4) void attn_kernel()
{
    extern __shared__ __align__(16) __half sma[];
    __shared__ int s_kept[32];
    __shared__ int s_cnt;
    const uint32_t sb = smem_u32(sma);

    const int tid  = threadIdx.x;
    const int wid  = tid >> 5;
    const int lane = tid & 31;
    const int row  = blockIdx.x;
    const int m    = row % MM;
    const int h    = (row / MM) % HH;
    const int b    = row / (MM * HH);
    const int tok0 = b * NN + m * BSZ;
    const size_t hoff = (size_t)h * HDD;

    const int pr = tid >> 3;
    const int pc = (tid & 7) << 3;

    // ---- group A: Q hi/lo loads (into stage1 region) ----
#pragma unroll
    for (int j = 0; j < 4; j++) {
        int r = pr + (j << 4);
        size_t g = (size_t)(tok0 + r) * DD + hoff + pc;
        uint32_t so = sb + (uint32_t)((r * APAD + pc) << 1);
        cp16(so + (ATQH << 1), g_qh2 + g);
        cp16(so + (ATQL << 1), g_ql2 + g);
    }
    asm volatile("cp.async.commit_group;" ::: "memory");

    // ---- fused mask on warp 0 (overlapped with Q loads) ----
    if (wid == 0) {
        const float* qbv = g_qb + (size_t)row * HDD;
        const float* kbv = g_kb + ((size_t)(row / MM) * MM + lane) * HDD;
        float s = 0.0f;
#pragma unroll
        for (int d4 = 0; d4 < 16; d4++) {
            float4 qv = *(const float4*)(qbv + (d4 << 2));
            float4 kv = *(const float4*)(kbv + (d4 << 2));
            s = fmaf(qv.x, kv.x, s); s = fmaf(qv.y, kv.y, s);
            s = fmaf(qv.z, kv.z, s); s = fmaf(qv.w, kv.w, s);
        }
        s *= SCALEF;
        const unsigned FULL = 0xffffffffu;
        float m1 = s;
#pragma unroll
        for (int off = 16; off; off >>= 1) m1 = fmaxf(m1, __shfl_xor_sync(FULL, m1, off));
        unsigned b1 = __ballot_sync(FULL, s == m1);
        int lead = __ffs(b1) - 1;
        float v2 = (lane == lead) ? -INFINITY : s;
        float m2 = v2;
#pragma unroll
        for (int off = 16; off; off >>= 1) m2 = fmaxf(m2, __shfl_xor_sync(FULL, m2, off));
        bool keep = (s >= m2) || (lane == m);
        unsigned km = __ballot_sync(FULL, keep);
        if (lane == 0) s_cnt = __popc(km);
        if (keep) {
            int pos = __popc(km & ((1u << lane) - 1u));
            s_kept[pos] = lane;
        }
    }
    __syncthreads();
    const int cnt = s_cnt;

    // ---- group B: tile 0 prefetch into stage0 (base ATSTG) ----
    {
        const int kt = b * NN + s_kept[0] * BSZ;
#pragma unroll
        for (int j = 0; j < 4; j++) {
            int r = pr + (j << 4);
            size_t g = (size_t)(kt + r) * DD + hoff + pc;
            uint32_t so = sb + (uint32_t)((ATSTG + r * APAD + pc) << 1);
            cp16(so,                 g_kh2 + g);
            cp16(so + (4608u << 1),  g_kl2 + g);
            cp16(so + (9216u << 1),  g_vf  + g);
        }
        asm volatile("cp.async.commit_group;" ::: "memory");
    }

    // fragment offsets
    uint32_t qab;
    {
        int mrow = wid * 16 + (lane & 15);
        qab = sb + (uint32_t)((mrow * APAD + ((lane >> 4) << 3)) << 1);
    }
    uint32_t kboff[4], voff[4];
#pragma unroll
    for (int np = 0; np < 4; np++) {
        int nrow = np * 16 + ((lane >> 4) << 3) + (lane & 7);
        int ke   = ((lane >> 3) & 1) << 3;
        kboff[np] = (uint32_t)((nrow * APAD + ke) << 1);
    }
#pragma unroll
    for (int dp = 0; dp < 4; dp++) {
        int vrow = (((lane >> 3) & 1) << 3) + (lane & 7);
        int vcol = dp * 16 + ((lane >> 4) << 3);
        voff[dp] = (uint32_t)((vrow * APAD + vcol) << 1);
    }

    // ---- hoist Q fragments: wait Q group, load, barrier before any
    //      stage1 (overlaid) write ----
    asm volatile("cp.async.wait_group 1;" ::: "memory");   // Q complete
    __syncthreads();                                        // all Q copies visible
    uint32_t qh_a[4][4], ql_a[4][4];
#pragma unroll
    for (int ks = 0; ks < 4; ks++) {
        ldm4(qh_a[ks], qab + (ATQH << 1) + ks * 32);
        ldm4(ql_a[ks], qab + (ATQL << 1) + ks * 32);
    }
    __syncthreads();                                        // Q reads done

    float c_o[8][4];
#pragma unroll
    for (int dt = 0; dt < 8; dt++)
#pragma unroll
        for (int r = 0; r < 4; r++) c_o[dt][r] = 0.0f;
    float mrun0 = -INFINITY, mrun1 = -INFINITY, lrun0 = 0.0f, lrun1 = 0.0f;

    for (int kbi = 0; kbi < cnt; kbi++) {
        if (kbi + 1 < cnt) {
            const int kt = b * NN + s_kept[kbi + 1] * BSZ;
            // stage for tile (kbi+1): odd -> stage1 (base 0, overlays Q)
            const uint32_t stb = ((kbi + 1) & 1) ? 0u : ATSTG;
#pragma unroll
            for (int j = 0; j < 4; j++) {
                int r = pr + (j << 4);
                size_t g = (size_t)(kt + r) * DD + hoff + pc;
                uint32_t so = sb + (uint32_t)((stb + r * APAD + pc) << 1);
                cp16(so,                g_kh2 + g);
                cp16(so + (4608u << 1), g_kl2 + g);
                cp16(so + (9216u << 1), g_vf  + g);
            }
        }
        asm volatile("cp.async.commit_group;" ::: "memory");
        if (kbi + 1 < cnt)
            asm volatile("cp.async.wait_group 1;" ::: "memory");
        else
            asm volatile("cp.async.wait_group 0;" ::: "memory");
        __syncthreads();

        const uint32_t stg = sb + (uint32_t)((((kbi & 1) ? 0u : ATSTG)) << 1);

        float c_s[8][4];
#pragma unroll
        for (int nt = 0; nt < 8; nt++)
#pragma unroll
            for (int r = 0; r < 4; r++) c_s[nt][r] = 0.0f;
#pragma unroll
        for (int ks = 0; ks < 4; ks++) {
            uint32_t kh[4][4], kl[4][4];
#pragma unroll
            for (int np = 0; np < 4; np++) {
                ldm4(kh[np], stg + kboff[np] + ks * 32);
                ldm4(kl[np], stg + (4608u << 1) + kboff[np] + ks * 32);
            }
#pragma unroll
            for (int nt = 0; nt < 8; nt++)
                MMA_F16(c_s[nt], qh_a[ks], &kh[nt >> 1][(nt & 1) << 1]);
#pragma unroll
            for (int nt = 0; nt < 8; nt++)
                MMA_F16(c_s[nt], qh_a[ks], &kl[nt >> 1][(nt & 1) << 1]);
#pragma unroll
            for (int nt = 0; nt < 8; nt++)
                MMA_F16(c_s[nt], ql_a[ks], &kh[nt >> 1][(nt & 1) << 1]);
        }

        const unsigned FULL = 0xffffffffu;
        float rmax0 = -INFINITY, rmax1 = -INFINITY;
#pragma unroll
        for (int nt = 0; nt < 8; nt++) {
            rmax0 = fmaxf(rmax0, fmaxf(c_s[nt][0], c_s[nt][1]));
            rmax1 = fmaxf(rmax1, fmaxf(c_s[nt][2], c_s[nt][3]));
        }
        rmax0 = fmaxf(rmax0, __shfl_xor_sync(FULL, rmax0, 1));
        rmax0 = fmaxf(rmax0, __shfl_xor_sync(FULL, rmax0, 2));
        rmax1 = fmaxf(rmax1, __shfl_xor_sync(FULL, rmax1, 1));
        rmax1 = fmaxf(rmax1, __shfl_xor_sync(FULL, rmax1, 2));

        float mn0 = fmaxf(mrun0, rmax0), mn1 = fmaxf(mrun1, rmax1);
        float e0 = __expf(mrun0 - mn0),  e1 = __expf(mrun1 - mn1);
        float rs0 = 0.0f, rs1 = 0.0f;
#pragma unroll
        for (int nt = 0; nt < 8; nt++) {
            c_s[nt][0] = __expf(c_s[nt][0] - mn0); rs0 += c_s[nt][0];
            c_s[nt][1] = __expf(c_s[nt][1] - mn0); rs0 += c_s[nt][1];
            c_s[nt][2] = __expf(c_s[nt][2] - mn1); rs1 += c_s[nt][2];
            c_s[nt][3] = __expf(c_s[nt][3] - mn1); rs1 += c_s[nt][3];
        }
        rs0 += __shfl_xor_sync(FULL, rs0, 1); rs0 += __shfl_xor_sync(FULL, rs0, 2);
        rs1 += __shfl_xor_sync(FULL, rs1, 1); rs1 += __shfl_xor_sync(FULL, rs1, 2);
        lrun0 = lrun0 * e0 + rs0;  lrun1 = lrun1 * e1 + rs1;
        mrun0 = mn0;               mrun1 = mn1;
#pragma unroll
        for (int dt = 0; dt < 8; dt++) {
            c_o[dt][0] *= e0; c_o[dt][1] *= e0;
            c_o[dt][2] *= e1; c_o[dt][3] *= e1;
        }

#pragma unroll
        for (int ks = 0; ks < 4; ks++) {
            uint32_t pA[4], pL[4];
#pragma unroll
            for (int half = 0; half < 2; half++) {
                const float* cs = c_s[2 * ks + half];
                float x0 = cs[0], x1 = cs[1], x2 = cs[2], x3 = cs[3];
                __half h0 = __float2half_rn(x0), h1 = __float2half_rn(x1);
                __half h2 = __float2half_rn(x2), h3 = __float2half_rn(x3);
                pA[2 * half]     = (uint32_t)__half_as_ushort(h0) |
                                   ((uint32_t)__half_as_ushort(h1) << 16);
                pA[2 * half + 1] = (uint32_t)__half_as_ushort(h2) |
                                   ((uint32_t)__half_as_ushort(h3) << 16);
                pL[2 * half]     = pack2f16(x0 - __half2float(h0),
                                            x1 - __half2float(h1));
                pL[2 * half + 1] = pack2f16(x2 - __half2float(h2),
                                            x3 - __half2float(h3));
            }
            uint32_t vf[4][4];
#pragma unroll
            for (int dp = 0; dp < 4; dp++)
                ldm4t(vf[dp], stg + (9216u << 1) + voff[dp]
                              + (uint32_t)(ks * 16 * APAD * 2));
#pragma unroll
            for (int dt = 0; dt < 8; dt++)
                MMA_F16(c_o[dt], pA, &vf[dt >> 1][(dt & 1) << 1]);
#pragma unroll
            for (int dt = 0; dt < 8; dt++)
                MMA_F16(c_o[dt], pL, &vf[dt >> 1][(dt & 1) << 1]);
        }
        __syncthreads();
    }

    const float inv0 = 1.0f / lrun0, inv1 = 1.0f / lrun1;
    const int g = lane >> 2, t = lane & 3;
    const int tk = tok0 + wid * 16 + g;
    const size_t o0 = (size_t)tk * DD + hoff;
    const size_t o1 = o0 + (size_t)8 * DD;
#pragma unroll
    for (int dt = 0; dt < 8; dt++) {
        int col = dt * 8 + t * 2;
        *(uint32_t*)(g_ah + o0 + col) = pack2f16(c_o[dt][0] * inv0, c_o[dt][1] * inv0);
        *(uint32_t*)(g_ah + o1 + col) = pack2f16(c_o[dt][2] * inv1, c_o[dt][3] * inv1);
    }
}

// =====================================================================
// Launch
// =====================================================================
extern "C" void kernel_launch(void* const* d_in, const int* in_sizes, int n_in,
                              void* d_out, int out_size)
{
    const float* x = nullptr; const float* qkv_w = nullptr;
    const float* proj_w = nullptr; const float* proj_b = nullptr;
    for (int i = 0; i < n_in; i++) {
        if      (in_sizes[i] == BB * NN * DD) x      = (const float*)d_in[i];
        else if (in_sizes[i] == 3 * DD * DD)  qkv_w  = (const float*)d_in[i];
        else if (in_sizes[i] == DD * DD)      proj_w = (const float*)d_in[i];
        else if (in_sizes[i] == DD)           proj_b = (const float*)d_in[i];
    }
    float* out = (float*)d_out;

    void* p;
    __half *xh, *wq, *wp, *ah;
    cudaGetSymbolAddress(&p, g_xh); xh = (__half*)p;
    cudaGetSymbolAddress(&p, g_wq); wq = (__half*)p;
    cudaGetSymbolAddress(&p, g_wp); wp = (__half*)p;
    cudaGetSymbolAddress(&p, g_ah); ah = (__half*)p;

    static int attr_done = 0;
    if (!attr_done) {
        cudaFuncSetAttribute(gemm_mma<0>, cudaFuncAttributeMaxDynamicSharedMemorySize, GEMM_SMEM);
        cudaFuncSetAttribute(gemm_mma<1>, cudaFuncAttributeMaxDynamicSharedMemorySize, GEMM_SMEM);
        cudaFuncSetAttribute(attn_kernel, cudaFuncAttributeMaxDynamicSharedMemorySize, ATT_SMEM);
        attr_done = 1;
    }

    {
        int n4 = N4_X + N4_WQ + N4_WP;
        split3_kernel<<<(n4 + 255) / 256, 256>>>(x, xh, qkv_w, wq, proj_w, wp);
    }
    gemm_mma<0><<<dim3(3 * DD / 128, TOK / 128), 256, GEMM_SMEM>>>(
        xh, wq, nullptr, nullptr, 3 * DD, DD);
    attn_kernel<<<BB * HH * MM, 128, ATT_SMEM>>>();
    gemm_mma<1><<<dim3(DD / 128, TOK / 128), 256, GEMM_SMEM>>>(
        ah, wp, proj_b, out, DD, DD);
}